// round 2
// baseline (speedup 1.0000x reference)
#include <cuda_runtime.h>
#include <math.h>
#include <stdint.h>

#define NSRC 4096
#define NTGT 4096
#define DIM  512
#define NCLS 64
#define KNN  10
#define RK   20
#define TOPN 2048
#define TAU  0.05f
#define EPSL 1e-6f

#define FORD_NEGINF 0x007FFFFFu  // ordered-uint encoding of -INF

// ---------------- scratch (device globals; allocation-free) ----------------
__device__ float g_Sn [NSRC * DIM];
__device__ float g_Tn [NTGT * DIM];
__device__ float g_T0n[NTGT * DIM];
__device__ float g_simT [ (size_t)NTGT * NSRC ];
__device__ float g_sim0T[ (size_t)NTGT * NSRC ];
__device__ int   g_assigned[NTGT];
__device__ float g_scores[NTGT];
__device__ int   g_sel[NTGT];
__device__ float g_logt[NTGT];
__device__ int   g_nc;

__device__ __forceinline__ unsigned int ford(float f) {
    unsigned int u = __float_as_uint(f);
    return (u & 0x80000000u) ? ~u : (u | 0x80000000u);
}

// ---------------- 1. normalize rows ----------------
__global__ void __launch_bounds__(128) normalize_k(
    const float* __restrict__ src, const float* __restrict__ tgt,
    const float* __restrict__ tgt0)
{
    const int r = blockIdx.x;
    const int m = blockIdx.y;
    if (r == 0 && m == 0 && threadIdx.x == 0) g_nc = 0;

    const float* in  = (m == 0) ? src  : (m == 1) ? tgt  : tgt0;
    float*       out = (m == 0) ? g_Sn : (m == 1) ? g_Tn : g_T0n;

    const float4 v = ((const float4*)(in + (size_t)r * DIM))[threadIdx.x];
    float s = v.x*v.x + v.y*v.y + v.z*v.z + v.w*v.w;
    #pragma unroll
    for (int o = 16; o; o >>= 1) s += __shfl_down_sync(0xffffffffu, s, o);
    __shared__ float ws[4];
    if ((threadIdx.x & 31) == 0) ws[threadIdx.x >> 5] = s;
    __syncthreads();
    const float tot = ws[0] + ws[1] + ws[2] + ws[3];
    const float inv = 1.0f / sqrtf(tot);
    float4 o4;
    o4.x = v.x * inv; o4.y = v.y * inv; o4.z = v.z * inv; o4.w = v.w * inv;
    ((float4*)(out + (size_t)r * DIM))[threadIdx.x] = o4;
}

// ---------------- 2. fp32 GEMM  C[4096,4096] = A(4096x512) * B(4096x512)^T --
// which==0 : C=g_simT,  A=g_Tn ; which==1 : C=g_sim0T, A=g_T0n ; B=g_Sn
__global__ void __launch_bounds__(256, 2) gemm_abT(int which)
{
    const float* __restrict__ A = which ? g_T0n : g_Tn;
    const float* __restrict__ B = g_Sn;
    float* __restrict__ C = which ? g_sim0T : g_simT;

    __shared__ float As[2][16][128];
    __shared__ float Bs[2][16][128];

    const int tid = threadIdx.x;
    const int bm = blockIdx.y * 128;
    const int bn = blockIdx.x * 128;
    const int ty = tid >> 4, tx = tid & 15;
    const int r0 = tid >> 2;           // 0..63
    const int kc = (tid & 3) * 4;      // 0,4,8,12

    const float* Ag0 = A + (size_t)(bm + r0)      * DIM + kc;
    const float* Ag1 = A + (size_t)(bm + r0 + 64) * DIM + kc;
    const float* Bg0 = B + (size_t)(bn + r0)      * DIM + kc;
    const float* Bg1 = B + (size_t)(bn + r0 + 64) * DIM + kc;

    // prologue: tile 0
    {
        float4 a0 = *(const float4*)(Ag0);
        float4 a1 = *(const float4*)(Ag1);
        float4 b0 = *(const float4*)(Bg0);
        float4 b1 = *(const float4*)(Bg1);
        As[0][kc+0][r0] = a0.x; As[0][kc+1][r0] = a0.y; As[0][kc+2][r0] = a0.z; As[0][kc+3][r0] = a0.w;
        As[0][kc+0][r0+64] = a1.x; As[0][kc+1][r0+64] = a1.y; As[0][kc+2][r0+64] = a1.z; As[0][kc+3][r0+64] = a1.w;
        Bs[0][kc+0][r0] = b0.x; Bs[0][kc+1][r0] = b0.y; Bs[0][kc+2][r0] = b0.z; Bs[0][kc+3][r0] = b0.w;
        Bs[0][kc+0][r0+64] = b1.x; Bs[0][kc+1][r0+64] = b1.y; Bs[0][kc+2][r0+64] = b1.z; Bs[0][kc+3][r0+64] = b1.w;
    }
    __syncthreads();

    float acc[8][8];
    #pragma unroll
    for (int i = 0; i < 8; ++i)
        #pragma unroll
        for (int jj = 0; jj < 8; ++jj) acc[i][jj] = 0.0f;

    float4 na0, na1, nb0, nb1;
    int cur = 0;
    for (int kt = 0; kt < 32; ++kt) {
        if (kt < 31) {
            const int ko = (kt + 1) * 16;
            na0 = *(const float4*)(Ag0 + ko);
            na1 = *(const float4*)(Ag1 + ko);
            nb0 = *(const float4*)(Bg0 + ko);
            nb1 = *(const float4*)(Bg1 + ko);
        }
        #pragma unroll
        for (int k = 0; k < 16; ++k) {
            float ar[8], br[8];
            *(float4*)&ar[0] = *(const float4*)&As[cur][k][ty * 8];
            *(float4*)&ar[4] = *(const float4*)&As[cur][k][ty * 8 + 4];
            *(float4*)&br[0] = *(const float4*)&Bs[cur][k][tx * 8];
            *(float4*)&br[4] = *(const float4*)&Bs[cur][k][tx * 8 + 4];
            #pragma unroll
            for (int i = 0; i < 8; ++i)
                #pragma unroll
                for (int jj = 0; jj < 8; ++jj)
                    acc[i][jj] = fmaf(ar[i], br[jj], acc[i][jj]);
        }
        if (kt < 31) {
            const int nxt = cur ^ 1;
            As[nxt][kc+0][r0] = na0.x; As[nxt][kc+1][r0] = na0.y; As[nxt][kc+2][r0] = na0.z; As[nxt][kc+3][r0] = na0.w;
            As[nxt][kc+0][r0+64] = na1.x; As[nxt][kc+1][r0+64] = na1.y; As[nxt][kc+2][r0+64] = na1.z; As[nxt][kc+3][r0+64] = na1.w;
            Bs[nxt][kc+0][r0] = nb0.x; Bs[nxt][kc+1][r0] = nb0.y; Bs[nxt][kc+2][r0] = nb0.z; Bs[nxt][kc+3][r0] = nb0.w;
            Bs[nxt][kc+0][r0+64] = nb1.x; Bs[nxt][kc+1][r0+64] = nb1.y; Bs[nxt][kc+2][r0+64] = nb1.z; Bs[nxt][kc+3][r0+64] = nb1.w;
            __syncthreads();
            cur = nxt;
        }
    }

    #pragma unroll
    for (int i = 0; i < 8; ++i) {
        float4 v0, v1;
        v0.x = acc[i][0]; v0.y = acc[i][1]; v0.z = acc[i][2]; v0.w = acc[i][3];
        v1.x = acc[i][4]; v1.y = acc[i][5]; v1.z = acc[i][6]; v1.w = acc[i][7];
        const size_t off = (size_t)(bm + ty * 8 + i) * NSRC + bn + tx * 8;
        *(float4*)(C + off)     = v0;
        *(float4*)(C + off + 4) = v1;
    }
}

// ---------------- 3. per-target: knn assign + masked top-20 score ----------
__global__ void __launch_bounds__(256) rank_kernel(
    const int* __restrict__ slab, const int* __restrict__ tlab)
{
    const int j = blockIdx.x;
    const int tid = threadIdx.x;

    __shared__ float s_sim[NSRC];
    __shared__ float s_sim0[NSRC];
    __shared__ unsigned char s_lab[NSRC];
    __shared__ unsigned long long s_red[8];
    __shared__ int   s_topi[KNN];
    __shared__ float s_topv[KNN];
    __shared__ int   s_a;

    const float* simrow  = g_simT  + (size_t)j * NSRC;
    const float* sim0row = g_sim0T + (size_t)j * NSRC;
    for (int i = tid; i < NSRC; i += 256) {
        s_sim[i]  = simrow[i];
        s_sim0[i] = sim0row[i];
        s_lab[i]  = (unsigned char)slab[i];
    }
    __syncthreads();

    // ---- top-10 overall (stable: val desc, idx asc) ----
    for (int it = 0; it < KNN; ++it) {
        float best = -INFINITY; int bi = 4095;
        for (int i = tid; i < NSRC; i += 256) {
            const float v = s_sim[i];
            if (v > best) { best = v; bi = i; }
        }
        unsigned long long key =
            ((unsigned long long)ford(best) << 12) | (unsigned)(4095 - bi);
        #pragma unroll
        for (int o = 16; o; o >>= 1) {
            unsigned long long other = __shfl_down_sync(0xffffffffu, key, o);
            if (other > key) key = other;
        }
        if ((tid & 31) == 0) s_red[tid >> 5] = key;
        __syncthreads();
        if (tid == 0) {
            unsigned long long k = s_red[0];
            #pragma unroll
            for (int w = 1; w < 8; ++w) if (s_red[w] > k) k = s_red[w];
            const int idx = 4095 - (int)(k & 0xFFFu);
            s_topi[it] = idx;
            s_topv[it] = s_sim[idx];
            s_sim[idx] = -INFINITY;
        }
        __syncthreads();
    }

    // ---- assigned label (first-max argmax over class counts) ----
    if (tid == 0) {
        int counts[NCLS];
        #pragma unroll
        for (int c = 0; c < NCLS; ++c) counts[c] = 0;
        for (int k = 0; k < KNN; ++k) counts[s_lab[s_topi[k]]]++;
        int a = 0, bc = counts[0];
        for (int c = 1; c < NCLS; ++c)
            if (counts[c] > bc) { bc = counts[c]; a = c; }
        s_a = a;
        g_assigned[j] = a;
        if (a == tlab[j]) atomicAdd(&g_nc, 1);
        for (int k = 0; k < KNN; ++k) s_sim[s_topi[k]] = s_topv[k];  // restore
    }
    __syncthreads();
    const int a = s_a;

    // ---- top-20 sum of sim0 within class / outside class ----
    float sumT = 0.0f, sumF = 0.0f;
    for (int pass = 0; pass < 2; ++pass) {
        float acc = 0.0f;
        for (int it = 0; it < RK; ++it) {
            float best = -INFINITY; int bi = 4095;
            for (int i = tid; i < NSRC; i += 256) {
                const bool in = (pass == 0) ? (s_lab[i] == a) : (s_lab[i] != a);
                if (in) {
                    const float v = s_sim[i];
                    if (v > best) { best = v; bi = i; }
                }
            }
            unsigned long long key =
                ((unsigned long long)ford(best) << 12) | (unsigned)(4095 - bi);
            #pragma unroll
            for (int o = 16; o; o >>= 1) {
                unsigned long long other = __shfl_down_sync(0xffffffffu, key, o);
                if (other > key) key = other;
            }
            if ((tid & 31) == 0) s_red[tid >> 5] = key;
            __syncthreads();
            if (tid == 0) {
                unsigned long long k = s_red[0];
                #pragma unroll
                for (int w = 1; w < 8; ++w) if (s_red[w] > k) k = s_red[w];
                if ((unsigned)(k >> 12) != FORD_NEGINF) {
                    const int idx = 4095 - (int)(k & 0xFFFu);
                    acc += s_sim0[idx];
                    s_sim[idx] = -INFINITY;  // consume
                }
                s_red[0] = k;
            }
            __syncthreads();
            const unsigned long long k = s_red[0];
            __syncthreads();  // protect s_red before next iteration's writes
            if ((unsigned)(k >> 12) == FORD_NEGINF) break;  // group exhausted
        }
        if (pass == 0) sumT = acc; else sumF = acc;
    }
    if (tid == 0) g_scores[j] = sumT / sumF;
}

// ---------------- 4. exact top-2048 membership (lax.top_k tie rules) -------
__global__ void __launch_bounds__(256) select_kernel()
{
    const int j = blockIdx.x;
    const int tid = threadIdx.x;
    __shared__ int sr[8];
    const float sj = g_scores[j];
    int c = 0;
    for (int i = tid; i < NTGT; i += 256) {
        const float si = g_scores[i];
        if (si > sj || (si == sj && i < j)) ++c;
    }
    #pragma unroll
    for (int o = 16; o; o >>= 1) c += __shfl_down_sync(0xffffffffu, c, o);
    if ((tid & 31) == 0) sr[tid >> 5] = c;
    __syncthreads();
    if (tid == 0) {
        int r = 0;
        #pragma unroll
        for (int w = 0; w < 8; ++w) r += sr[w];
        g_sel[j] = (r < TOPN) ? 1 : 0;
    }
}

// ---------------- 5. contrast term per selected column ---------------------
__global__ void __launch_bounds__(256) contrast_kernel(const int* __restrict__ slab)
{
    const int j = blockIdx.x;
    const int tid = threadIdx.x;
    __shared__ float s_m[8];
    __shared__ float s_pA[8];
    __shared__ float s_pM[8];

    if (!g_sel[j]) { if (tid == 0) g_logt[j] = 0.0f; return; }

    const float* row = g_sim0T + (size_t)j * NSRC;
    const int a = g_assigned[j];

    float m = -INFINITY;
    for (int i = tid; i < NSRC; i += 256) m = fmaxf(m, row[i]);
    #pragma unroll
    for (int o = 16; o; o >>= 1) m = fmaxf(m, __shfl_down_sync(0xffffffffu, m, o));
    if ((tid & 31) == 0) s_m[tid >> 5] = m;
    __syncthreads();
    float mm = s_m[0];
    #pragma unroll
    for (int w = 1; w < 8; ++w) mm = fmaxf(mm, s_m[w]);

    float eA = 0.0f, eM = 0.0f;
    const float itau = 1.0f / TAU;
    for (int i = tid; i < NSRC; i += 256) {
        const float e = expf((row[i] - mm) * itau);
        eA += e;
        if (slab[i] == a) eM += e;
    }
    #pragma unroll
    for (int o = 16; o; o >>= 1) {
        eA += __shfl_down_sync(0xffffffffu, eA, o);
        eM += __shfl_down_sync(0xffffffffu, eM, o);
    }
    if ((tid & 31) == 0) { s_pA[tid >> 5] = eA; s_pM[tid >> 5] = eM; }
    __syncthreads();
    if (tid == 0) {
        float tA = 0.0f, tM = 0.0f;
        #pragma unroll
        for (int w = 0; w < 8; ++w) { tA += s_pA[w]; tM += s_pM[w]; }
        g_logt[j] = logf(tM / tA + EPSL);
    }
}

// ---------------- 6. final deterministic reduction --------------------------
__global__ void __launch_bounds__(256) finalize_kernel(float* out, int out_size)
{
    const int tid = threadIdx.x;
    __shared__ float sr[8];
    float acc = 0.0f;
    for (int i = tid; i < NTGT; i += 256) acc += g_logt[i];
    #pragma unroll
    for (int o = 16; o; o >>= 1) acc += __shfl_down_sync(0xffffffffu, acc, o);
    if ((tid & 31) == 0) sr[tid >> 5] = acc;
    __syncthreads();
    if (tid == 0) {
        float tot = 0.0f;
        #pragma unroll
        for (int w = 0; w < 8; ++w) tot += sr[w];
        out[0] = -(tot / (float)TOPN);
        if (out_size > 1) out[1] = (float)g_nc;
    }
}

// ---------------- host launcher ---------------------------------------------
extern "C" void kernel_launch(void* const* d_in, const int* in_sizes, int n_in,
                              void* d_out, int out_size)
{
    const float* src  = (const float*)d_in[0];
    const int*   slab = (const int*)  d_in[1];
    const float* tgt  = (const float*)d_in[2];
    const float* tgt0 = (const float*)d_in[3];
    const int*   tlab = (const int*)  d_in[4];
    float* out = (float*)d_out;

    normalize_k<<<dim3(NSRC, 3), 128>>>(src, tgt, tgt0);
    gemm_abT<<<dim3(32, 32), 256>>>(0);   // simT  = Tn  @ Sn^T
    gemm_abT<<<dim3(32, 32), 256>>>(1);   // sim0T = T0n @ Sn^T
    rank_kernel<<<NTGT, 256>>>(slab, tlab);
    select_kernel<<<NTGT, 256>>>();
    contrast_kernel<<<NTGT, 256>>>(slab);
    finalize_kernel<<<1, 256>>>(out, out_size);
}

// round 5
// speedup vs baseline: 1.2677x; 1.2677x over previous
#include <cuda_runtime.h>
#include <cuda_bf16.h>
#include <math.h>
#include <stdint.h>

#define NSRC 4096
#define NTGT 4096
#define DIM  512
#define KSPL 1536          // 3*DIM split-K for bf16 sim0 GEMM
#define NCLS 64
#define KNN  10
#define RK   20
#define TOPN 2048
#define TAU  0.05f
#define EPSL 1e-6f

#define FORD_NEGINF 0x007FFFFFu  // ordered-uint encoding of -INF

// ---------------- scratch (device globals; allocation-free) ----------------
__device__ float g_Sn [NSRC * DIM];
__device__ float g_Tn [NTGT * DIM];
__device__ __nv_bfloat16 g_A16[(size_t)NTGT * KSPL];  // T0 split: [hi|hi|lo]
__device__ __nv_bfloat16 g_B16[(size_t)NSRC * KSPL];  // S  split: [hi|lo|hi]
__device__ float g_simT [ (size_t)NTGT * NSRC ];
__device__ float g_sim0T[ (size_t)NTGT * NSRC ];
__device__ int   g_assigned[NTGT];
__device__ float g_scores[NTGT];
__device__ int   g_sel[NTGT];
__device__ float g_logt[NTGT];
__device__ int   g_nc;

__device__ __forceinline__ unsigned int ford(float f) {
    unsigned int u = __float_as_uint(f);
    return (u & 0x80000000u) ? ~u : (u | 0x80000000u);
}

__device__ __forceinline__ unsigned long long wmax(unsigned long long k) {
    #pragma unroll
    for (int o = 16; o; o >>= 1) {
        unsigned long long t = __shfl_xor_sync(0xffffffffu, k, o);
        if (t > k) k = t;
    }
    return k;
}

__device__ __forceinline__ void ldsm4(uint32_t* r, uint32_t addr) {
    asm volatile("ldmatrix.sync.aligned.m8n8.x4.shared.b16 {%0,%1,%2,%3}, [%4];"
        : "=r"(r[0]), "=r"(r[1]), "=r"(r[2]), "=r"(r[3]) : "r"(addr));
}
__device__ __forceinline__ void ldsm2(uint32_t* r, uint32_t addr) {
    asm volatile("ldmatrix.sync.aligned.m8n8.x2.shared.b16 {%0,%1}, [%2];"
        : "=r"(r[0]), "=r"(r[1]) : "r"(addr));
}
__device__ __forceinline__ void mma16816(float* c, const uint32_t* a, const uint32_t* b) {
    asm volatile("mma.sync.aligned.m16n8k16.row.col.f32.bf16.bf16.f32 "
        "{%0,%1,%2,%3}, {%4,%5,%6,%7}, {%8,%9}, {%0,%1,%2,%3};"
        : "+f"(c[0]), "+f"(c[1]), "+f"(c[2]), "+f"(c[3])
        : "r"(a[0]), "r"(a[1]), "r"(a[2]), "r"(a[3]), "r"(b[0]), "r"(b[1]));
}

// ---------------- 1. normalize rows (+ bf16 hi/lo split emission) ----------
__global__ void __launch_bounds__(128) normalize_k(
    const float* __restrict__ src, const float* __restrict__ tgt,
    const float* __restrict__ tgt0)
{
    const int r = blockIdx.x;
    const int m = blockIdx.y;
    if (r == 0 && m == 0 && threadIdx.x == 0) g_nc = 0;

    const float* in = (m == 0) ? src : (m == 1) ? tgt : tgt0;

    const float4 v = ((const float4*)(in + (size_t)r * DIM))[threadIdx.x];
    float s = v.x*v.x + v.y*v.y + v.z*v.z + v.w*v.w;
    #pragma unroll
    for (int o = 16; o; o >>= 1) s += __shfl_down_sync(0xffffffffu, s, o);
    __shared__ float ws[4];
    if ((threadIdx.x & 31) == 0) ws[threadIdx.x >> 5] = s;
    __syncthreads();
    const float tot = ws[0] + ws[1] + ws[2] + ws[3];
    const float inv = 1.0f / sqrtf(tot);
    float o4[4];
    o4[0] = v.x * inv; o4[1] = v.y * inv; o4[2] = v.z * inv; o4[3] = v.w * inv;

    if (m == 0 || m == 1) {
        float* out = (m == 0) ? g_Sn : g_Tn;
        ((float4*)(out + (size_t)r * DIM))[threadIdx.x] =
            make_float4(o4[0], o4[1], o4[2], o4[3]);
    }
    if (m == 0 || m == 2) {
        __nv_bfloat16 h[4], l[4];
        #pragma unroll
        for (int t = 0; t < 4; ++t) {
            h[t] = __float2bfloat16_rn(o4[t]);
            l[t] = __float2bfloat16_rn(o4[t] - __bfloat162float(h[t]));
        }
        const int c = threadIdx.x * 4;
        if (m == 0) {  // B' = [hi | lo | hi]
            __nv_bfloat16* bp = g_B16 + (size_t)r * KSPL;
            #pragma unroll
            for (int t = 0; t < 4; ++t) {
                bp[c + t]        = h[t];
                bp[c + t + 512]  = l[t];
                bp[c + t + 1024] = h[t];
            }
        } else {       // A' = [hi | hi | lo]
            __nv_bfloat16* ap = g_A16 + (size_t)r * KSPL;
            #pragma unroll
            for (int t = 0; t < 4; ++t) {
                ap[c + t]        = h[t];
                ap[c + t + 512]  = h[t];
                ap[c + t + 1024] = l[t];
            }
        }
    }
}

// ---------------- 2a. fp32 GEMM  simT = Tn @ Sn^T (exact; knn-critical) ----
__global__ void __launch_bounds__(256, 2) gemm_abT()
{
    const float* __restrict__ A = g_Tn;
    const float* __restrict__ B = g_Sn;
    float* __restrict__ C = g_simT;

    __shared__ float As[2][16][128];
    __shared__ float Bs[2][16][128];

    const int tid = threadIdx.x;
    const int bm = blockIdx.y * 128;
    const int bn = blockIdx.x * 128;
    const int ty = tid >> 4, tx = tid & 15;
    const int r0 = tid >> 2;
    const int kc = (tid & 3) * 4;

    const float* Ag0 = A + (size_t)(bm + r0)      * DIM + kc;
    const float* Ag1 = A + (size_t)(bm + r0 + 64) * DIM + kc;
    const float* Bg0 = B + (size_t)(bn + r0)      * DIM + kc;
    const float* Bg1 = B + (size_t)(bn + r0 + 64) * DIM + kc;

    {
        float4 a0 = *(const float4*)(Ag0);
        float4 a1 = *(const float4*)(Ag1);
        float4 b0 = *(const float4*)(Bg0);
        float4 b1 = *(const float4*)(Bg1);
        As[0][kc+0][r0] = a0.x; As[0][kc+1][r0] = a0.y; As[0][kc+2][r0] = a0.z; As[0][kc+3][r0] = a0.w;
        As[0][kc+0][r0+64] = a1.x; As[0][kc+1][r0+64] = a1.y; As[0][kc+2][r0+64] = a1.z; As[0][kc+3][r0+64] = a1.w;
        Bs[0][kc+0][r0] = b0.x; Bs[0][kc+1][r0] = b0.y; Bs[0][kc+2][r0] = b0.z; Bs[0][kc+3][r0] = b0.w;
        Bs[0][kc+0][r0+64] = b1.x; Bs[0][kc+1][r0+64] = b1.y; Bs[0][kc+2][r0+64] = b1.z; Bs[0][kc+3][r0+64] = b1.w;
    }
    __syncthreads();

    float acc[8][8];
    #pragma unroll
    for (int i = 0; i < 8; ++i)
        #pragma unroll
        for (int jj = 0; jj < 8; ++jj) acc[i][jj] = 0.0f;

    float4 na0, na1, nb0, nb1;
    int cur = 0;
    for (int kt = 0; kt < 32; ++kt) {
        if (kt < 31) {
            const int ko = (kt + 1) * 16;
            na0 = *(const float4*)(Ag0 + ko);
            na1 = *(const float4*)(Ag1 + ko);
            nb0 = *(const float4*)(Bg0 + ko);
            nb1 = *(const float4*)(Bg1 + ko);
        }
        #pragma unroll
        for (int k = 0; k < 16; ++k) {
            float ar[8], br[8];
            *(float4*)&ar[0] = *(const float4*)&As[cur][k][ty * 8];
            *(float4*)&ar[4] = *(const float4*)&As[cur][k][ty * 8 + 4];
            *(float4*)&br[0] = *(const float4*)&Bs[cur][k][tx * 8];
            *(float4*)&br[4] = *(const float4*)&Bs[cur][k][tx * 8 + 4];
            #pragma unroll
            for (int i = 0; i < 8; ++i)
                #pragma unroll
                for (int jj = 0; jj < 8; ++jj)
                    acc[i][jj] = fmaf(ar[i], br[jj], acc[i][jj]);
        }
        if (kt < 31) {
            const int nxt = cur ^ 1;
            As[nxt][kc+0][r0] = na0.x; As[nxt][kc+1][r0] = na0.y; As[nxt][kc+2][r0] = na0.z; As[nxt][kc+3][r0] = na0.w;
            As[nxt][kc+0][r0+64] = na1.x; As[nxt][kc+1][r0+64] = na1.y; As[nxt][kc+2][r0+64] = na1.z; As[nxt][kc+3][r0+64] = na1.w;
            Bs[nxt][kc+0][r0] = nb0.x; Bs[nxt][kc+1][r0] = nb0.y; Bs[nxt][kc+2][r0] = nb0.z; Bs[nxt][kc+3][r0] = nb0.w;
            Bs[nxt][kc+0][r0+64] = nb1.x; Bs[nxt][kc+1][r0+64] = nb1.y; Bs[nxt][kc+2][r0+64] = nb1.z; Bs[nxt][kc+3][r0+64] = nb1.w;
            __syncthreads();
            cur = nxt;
        }
    }

    #pragma unroll
    for (int i = 0; i < 8; ++i) {
        float4 v0, v1;
        v0.x = acc[i][0]; v0.y = acc[i][1]; v0.z = acc[i][2]; v0.w = acc[i][3];
        v1.x = acc[i][4]; v1.y = acc[i][5]; v1.z = acc[i][6]; v1.w = acc[i][7];
        const size_t off = (size_t)(bm + ty * 8 + i) * NSRC + bn + tx * 8;
        *(float4*)(C + off)     = v0;
        *(float4*)(C + off + 4) = v1;
    }
}

// ---------------- 2b. bf16 split GEMM  sim0T = A'(4096x1536) @ B'^T --------
// mma.sync m16n8k16, 128x128 tile, 8 warps of 64x32, K step 32.
// smem rows padded to 40 bf16 (80 B): ldmatrix conflict-free.
__global__ void __launch_bounds__(256) gemm_bf16_sim0()
{
    __shared__ __nv_bfloat16 As[2][128][40];
    __shared__ __nv_bfloat16 Bs[2][128][40];

    const int tid = threadIdx.x;
    const int bm = blockIdx.y * 128;
    const int bn = blockIdx.x * 128;
    const int lr = tid >> 1;       // 0..127: row loaded by this thread
    const int lh = tid & 1;        // k half: 0 or 16

    const __nv_bfloat16* Ag = g_A16 + (size_t)(bm + lr) * KSPL + lh * 16;
    const __nv_bfloat16* Bg = g_B16 + (size_t)(bn + lr) * KSPL + lh * 16;

    const int w = tid >> 5, lane = tid & 31;
    const int wm = (w >> 2) * 64;  // 0 / 64
    const int wn = (w & 3) * 32;   // 0 / 32 / 64 / 96

    const uint32_t sA0 = (uint32_t)__cvta_generic_to_shared(&As[0][0][0]);
    const uint32_t sB0 = (uint32_t)__cvta_generic_to_shared(&Bs[0][0][0]);
    const uint32_t BUF = 128 * 40 * 2;  // 10240 B

    // per-lane ldmatrix row offsets (bytes) within a buffer
    const uint32_t aoff = (uint32_t)(wm + (lane & 15)) * 80u + (uint32_t)(lane >> 4) * 16u;
    const uint32_t boff = (uint32_t)(wn + (lane & 7))  * 80u + (uint32_t)((lane >> 3) & 1) * 16u;

    // prologue: k-tile 0 -> buffer 0
    {
        uint4 a0 = *(const uint4*)(Ag);
        uint4 a1 = *(const uint4*)(Ag + 8);
        uint4 b0 = *(const uint4*)(Bg);
        uint4 b1 = *(const uint4*)(Bg + 8);
        *(uint4*)&As[0][lr][lh * 16]     = a0;
        *(uint4*)&As[0][lr][lh * 16 + 8] = a1;
        *(uint4*)&Bs[0][lr][lh * 16]     = b0;
        *(uint4*)&Bs[0][lr][lh * 16 + 8] = b1;
    }
    __syncthreads();

    float acc[4][4][4];
    #pragma unroll
    for (int mi = 0; mi < 4; ++mi)
        #pragma unroll
        for (int ni = 0; ni < 4; ++ni)
            #pragma unroll
            for (int t = 0; t < 4; ++t) acc[mi][ni][t] = 0.0f;

    int cur = 0;
    const int NKT = KSPL / 32;  // 48
    for (int kt = 0; kt < NKT; ++kt) {
        uint4 na0, na1, nb0, nb1;
        if (kt < NKT - 1) {
            const int ko = (kt + 1) * 32;
            na0 = *(const uint4*)(Ag + ko);
            na1 = *(const uint4*)(Ag + ko + 8);
            nb0 = *(const uint4*)(Bg + ko);
            nb1 = *(const uint4*)(Bg + ko + 8);
        }
        const uint32_t abase = sA0 + (uint32_t)cur * BUF + aoff;
        const uint32_t bbase = sB0 + (uint32_t)cur * BUF + boff;
        #pragma unroll
        for (int kc = 0; kc < 2; ++kc) {
            uint32_t afr[4][4], bfr[4][2];
            #pragma unroll
            for (int mi = 0; mi < 4; ++mi)
                ldsm4(afr[mi], abase + (uint32_t)mi * (16u * 80u) + (uint32_t)kc * 32u);
            #pragma unroll
            for (int ni = 0; ni < 4; ++ni)
                ldsm2(bfr[ni], bbase + (uint32_t)ni * (8u * 80u) + (uint32_t)kc * 32u);
            #pragma unroll
            for (int mi = 0; mi < 4; ++mi)
                #pragma unroll
                for (int ni = 0; ni < 4; ++ni)
                    mma16816(acc[mi][ni], afr[mi], bfr[ni]);
        }
        if (kt < NKT - 1) {
            const int nxt = cur ^ 1;
            __syncthreads();   // everyone done reading buf nxt from 2 tiles ago
            *(uint4*)&As[nxt][lr][lh * 16]     = na0;
            *(uint4*)&As[nxt][lr][lh * 16 + 8] = na1;
            *(uint4*)&Bs[nxt][lr][lh * 16]     = nb0;
            *(uint4*)&Bs[nxt][lr][lh * 16 + 8] = nb1;
            __syncthreads();
            cur = nxt;
        }
    }

    // epilogue: c0,c1 -> (row, col..col+1); c2,c3 -> (row+8, ...)
    float* __restrict__ C = g_sim0T;
    const int rbase = bm + wm + (lane >> 2);
    const int cbase = bn + wn + (lane & 3) * 2;
    #pragma unroll
    for (int mi = 0; mi < 4; ++mi) {
        #pragma unroll
        for (int ni = 0; ni < 4; ++ni) {
            const int rr = rbase + mi * 16;
            const int cc = cbase + ni * 8;
            *(float2*)(C + (size_t)rr * NSRC + cc)       = make_float2(acc[mi][ni][0], acc[mi][ni][1]);
            *(float2*)(C + (size_t)(rr + 8) * NSRC + cc) = make_float2(acc[mi][ni][2], acc[mi][ni][3]);
        }
    }
}

// ---------------- 3. per-target: warp-synchronous selection ----------------
__global__ void __launch_bounds__(256) rank_kernel(
    const int* __restrict__ slab, const int* __restrict__ tlab)
{
    const int j   = blockIdx.x;
    const int tid = threadIdx.x;
    const int lane = tid & 31;
    const int w    = tid >> 5;

    __shared__ float s_sim0[NSRC];
    __shared__ unsigned char s_lab[NSRC];
    __shared__ unsigned long long s_k10[80];
    __shared__ unsigned long long s_k20[2][160];
    __shared__ int   s_t10[KNN];
    __shared__ int   s_a;
    __shared__ float s_sum[2];

    const float* simrow  = g_simT  + (size_t)j * NSRC;
    const float* sim0row = g_sim0T + (size_t)j * NSRC;

    #pragma unroll
    for (int t = 0; t < 4; ++t) {
        const int i = tid + t * 256;
        ((float4*)s_sim0)[i] = ((const float4*)sim0row)[i];
        int4 lb = ((const int4*)slab)[i];
        uchar4 u;
        u.x = (unsigned char)lb.x; u.y = (unsigned char)lb.y;
        u.z = (unsigned char)lb.z; u.w = (unsigned char)lb.w;
        ((uchar4*)s_lab)[i] = u;
    }

    const int base = w * 512 + lane * 16;
    float v[16];
    {
        const float4* rp = (const float4*)(simrow + base);
        float4 a = rp[0], b = rp[1], c = rp[2], d = rp[3];
        v[0]=a.x; v[1]=a.y; v[2]=a.z;  v[3]=a.w;
        v[4]=b.x; v[5]=b.y; v[6]=b.z;  v[7]=b.w;
        v[8]=c.x; v[9]=c.y; v[10]=c.z; v[11]=c.w;
        v[12]=d.x; v[13]=d.y; v[14]=d.z; v[15]=d.w;
    }

    {
        unsigned int alive = 0xFFFFu;
        #pragma unroll 1
        for (int it = 0; it < KNN; ++it) {
            float best = -INFINITY; int bi = 0;
            #pragma unroll
            for (int i = 0; i < 16; ++i) {
                const float x = ((alive >> i) & 1u) ? v[i] : -INFINITY;
                if (x > best) { best = x; bi = i; }
            }
            unsigned long long key =
                ((unsigned long long)ford(best) << 12) | (unsigned)(4095 - (base + bi));
            key = wmax(key);
            if (lane == 0) s_k10[w * KNN + it] = key;
            const int widx = 4095 - (int)(key & 0xFFFu);
            const unsigned int d = (unsigned)(widx - base);
            if (d < 16u) alive &= ~(1u << d);
        }
    }
    __syncthreads();

    if (w == 0) {
        unsigned long long mk[3];
        mk[0] = s_k10[lane];
        mk[1] = s_k10[lane + 32];
        mk[2] = (lane < 16) ? s_k10[lane + 64] : 0ull;
        unsigned int al = 7u;
        #pragma unroll 1
        for (int it = 0; it < KNN; ++it) {
            unsigned long long b = 0ull;
            #pragma unroll
            for (int t = 0; t < 3; ++t)
                if ((al >> t) & 1u) b = (mk[t] > b) ? mk[t] : b;
            unsigned long long key = wmax(b);
            if (lane == 0) s_t10[it] = 4095 - (int)(key & 0xFFFu);
            #pragma unroll
            for (int t = 0; t < 3; ++t)
                if (mk[t] == key) al &= ~(1u << t);
        }
        if (lane == 0) {
            int cls[KNN];
            #pragma unroll
            for (int k = 0; k < KNN; ++k) cls[k] = s_lab[s_t10[k]];
            int bestc = 1000, bestn = 0;
            #pragma unroll 1
            for (int k = 0; k < KNN; ++k) {
                int n = 0;
                #pragma unroll
                for (int l = 0; l < KNN; ++l) n += (cls[l] == cls[k]);
                if (n > bestn || (n == bestn && cls[k] < bestc)) { bestn = n; bestc = cls[k]; }
            }
            s_a = bestc;
            g_assigned[j] = bestc;
            if (bestc == tlab[j]) atomicAdd(&g_nc, 1);
        }
    }
    __syncthreads();
    const int a = s_a;

    unsigned int inmask = 0u;
    #pragma unroll
    for (int i = 0; i < 16; ++i)
        inmask |= (s_lab[base + i] == a) ? (1u << i) : 0u;

    #pragma unroll 1
    for (int pass = 0; pass < 2; ++pass) {
        unsigned int al = pass ? (0xFFFFu & ~inmask) : inmask;
        int it = 0;
        #pragma unroll 1
        for (; it < RK; ++it) {
            float best = -INFINITY; int bi = 0;
            #pragma unroll
            for (int i = 0; i < 16; ++i) {
                const float x = ((al >> i) & 1u) ? v[i] : -INFINITY;
                if (x > best) { best = x; bi = i; }
            }
            unsigned long long key =
                ((unsigned long long)ford(best) << 12) | (unsigned)(4095 - (base + bi));
            key = wmax(key);
            if ((unsigned)(key >> 12) == FORD_NEGINF) break;
            if (lane == 0) s_k20[pass][w * RK + it] = key;
            const int widx = 4095 - (int)(key & 0xFFFu);
            const unsigned int d = (unsigned)(widx - base);
            if (d < 16u) al &= ~(1u << d);
        }
        for (; it < RK; ++it)
            if (lane == 0) s_k20[pass][w * RK + it] = 0ull;
    }
    __syncthreads();

    if (w < 2) {
        const unsigned long long* keys = s_k20[w];
        unsigned long long mk[5];
        #pragma unroll
        for (int t = 0; t < 5; ++t) mk[t] = keys[lane + 32 * t];
        unsigned int al = 0x1Fu;
        float acc = 0.0f;
        #pragma unroll 1
        for (int it = 0; it < RK; ++it) {
            unsigned long long b = 0ull;
            #pragma unroll
            for (int t = 0; t < 5; ++t)
                if ((al >> t) & 1u) b = (mk[t] > b) ? mk[t] : b;
            unsigned long long key = wmax(b);
            const unsigned int f = (unsigned)(key >> 12);
            if (f == 0u || f == FORD_NEGINF) break;
            acc += s_sim0[4095 - (int)(key & 0xFFFu)];
            #pragma unroll
            for (int t = 0; t < 5; ++t)
                if (mk[t] == key) al &= ~(1u << t);
        }
        if (lane == 0) s_sum[w] = acc;
    }
    __syncthreads();
    if (tid == 0) g_scores[j] = s_sum[0] / s_sum[1];
}

// ---------------- 4. exact top-2048 membership ------------------------------
__global__ void __launch_bounds__(256) select_kernel()
{
    const int j = blockIdx.x;
    const int tid = threadIdx.x;
    __shared__ int sr[8];
    const float sj = g_scores[j];
    int c = 0;
    for (int i = tid; i < NTGT; i += 256) {
        const float si = g_scores[i];
        if (si > sj || (si == sj && i < j)) ++c;
    }
    #pragma unroll
    for (int o = 16; o; o >>= 1) c += __shfl_down_sync(0xffffffffu, c, o);
    if ((tid & 31) == 0) sr[tid >> 5] = c;
    __syncthreads();
    if (tid == 0) {
        int r = 0;
        #pragma unroll
        for (int w = 0; w < 8; ++w) r += sr[w];
        g_sel[j] = (r < TOPN) ? 1 : 0;
    }
}

// ---------------- 5. contrast term per selected column ---------------------
__global__ void __launch_bounds__(256) contrast_kernel(const int* __restrict__ slab)
{
    const int j = blockIdx.x;
    const int tid = threadIdx.x;
    __shared__ float s_m[8];
    __shared__ float s_pA[8];
    __shared__ float s_pM[8];

    if (!g_sel[j]) { if (tid == 0) g_logt[j] = 0.0f; return; }

    const float* row = g_sim0T + (size_t)j * NSRC;
    const int a = g_assigned[j];

    float m = -INFINITY;
    for (int i = tid; i < NSRC; i += 256) m = fmaxf(m, row[i]);
    #pragma unroll
    for (int o = 16; o; o >>= 1) m = fmaxf(m, __shfl_down_sync(0xffffffffu, m, o));
    if ((tid & 31) == 0) s_m[tid >> 5] = m;
    __syncthreads();
    float mm = s_m[0];
    #pragma unroll
    for (int w = 1; w < 8; ++w) mm = fmaxf(mm, s_m[w]);

    float eA = 0.0f, eM = 0.0f;
    const float itau = 1.0f / TAU;
    for (int i = tid; i < NSRC; i += 256) {
        const float e = expf((row[i] - mm) * itau);
        eA += e;
        if (slab[i] == a) eM += e;
    }
    #pragma unroll
    for (int o = 16; o; o >>= 1) {
        eA += __shfl_down_sync(0xffffffffu, eA, o);
        eM += __shfl_down_sync(0xffffffffu, eM, o);
    }
    if ((tid & 31) == 0) { s_pA[tid >> 5] = eA; s_pM[tid >> 5] = eM; }
    __syncthreads();
    if (tid == 0) {
        float tA = 0.0f, tM = 0.0f;
        #pragma unroll
        for (int w = 0; w < 8; ++w) { tA += s_pA[w]; tM += s_pM[w]; }
        g_logt[j] = logf(tM / tA + EPSL);
    }
}

// ---------------- 6. final deterministic reduction --------------------------
__global__ void __launch_bounds__(256) finalize_kernel(float* out, int out_size)
{
    const int tid = threadIdx.x;
    __shared__ float sr[8];
    float acc = 0.0f;
    for (int i = tid; i < NTGT; i += 256) acc += g_logt[i];
    #pragma unroll
    for (int o = 16; o; o >>= 1) acc += __shfl_down_sync(0xffffffffu, acc, o);
    if ((tid & 31) == 0) sr[tid >> 5] = acc;
    __syncthreads();
    if (tid == 0) {
        float tot = 0.0f;
        #pragma unroll
        for (int w = 0; w < 8; ++w) tot += sr[w];
        out[0] = -(tot / (float)TOPN);
        if (out_size > 1) out[1] = (float)g_nc;
    }
}

// ---------------- host launcher ---------------------------------------------
extern "C" void kernel_launch(void* const* d_in, const int* in_sizes, int n_in,
                              void* d_out, int out_size)
{
    const float* src  = (const float*)d_in[0];
    const int*   slab = (const int*)  d_in[1];
    const float* tgt  = (const float*)d_in[2];
    const float* tgt0 = (const float*)d_in[3];
    const int*   tlab = (const int*)  d_in[4];
    float* out = (float*)d_out;

    normalize_k<<<dim3(NSRC, 3), 128>>>(src, tgt, tgt0);
    gemm_abT<<<dim3(32, 32), 256>>>();         // simT  (fp32 exact)
    gemm_bf16_sim0<<<dim3(32, 32), 256>>>();   // sim0T (split-bf16 tensor core)
    rank_kernel<<<NTGT, 256>>>(slab, tlab);
    select_kernel<<<NTGT, 256>>>();
    contrast_kernel<<<NTGT, 256>>>(slab);
    finalize_kernel<<<1, 256>>>(out, out_size);
}

// round 8
// speedup vs baseline: 1.2726x; 1.0039x over previous
#include <cuda_runtime.h>
#include <cuda_bf16.h>
#include <math.h>
#include <stdint.h>

#define NSRC 4096
#define NTGT 4096
#define DIM  512
#define KSIM 3072          // 6-term split-K for simT (ordering-only, err ~1e-9)
#define KSP0 1536          // 3-term split-K for sim0T (validated R5)
#define NCLS 64
#define KNN  10
#define RK   20
#define TOPN 2048
#define TAU  0.05f
#define EPSL 1e-6f

#define FORD_NEGINF 0x007FFFFFu

// ---------------- scratch (device globals; allocation-free) ----------------
__device__ __nv_bfloat16 g_TT16[(size_t)NTGT * KSIM];  // T  split [a0|a0|a1|a1|a0|a2]
__device__ __nv_bfloat16 g_TS16[(size_t)NSRC * KSIM];  // S  split [b0|b1|b0|b1|b2|b0]
__device__ __nv_bfloat16 g_A16 [(size_t)NTGT * KSP0];  // T0 split [h|h|l]
__device__ __nv_bfloat16 g_B16 [(size_t)NSRC * KSP0];  // S  split [h|l|h]
__device__ float g_simT [ (size_t)NTGT * NSRC ];
__device__ float g_sim0T[ (size_t)NTGT * NSRC ];
__device__ int   g_assigned[NTGT];
__device__ float g_scores[NTGT];
__device__ int   g_sel[NTGT];
__device__ float g_logt[NTGT];
__device__ int   g_nc;

// ---------------- helpers ---------------------------------------------------
__device__ __forceinline__ unsigned int ford(float f) {
    unsigned int u = __float_as_uint(f);
    return (u & 0x80000000u) ? ~u : (u | 0x80000000u);
}
__device__ __forceinline__ unsigned long long wmax(unsigned long long k) {
    #pragma unroll
    for (int o = 16; o; o >>= 1) {
        unsigned long long t = __shfl_xor_sync(0xffffffffu, k, o);
        if (t > k) k = t;
    }
    return k;
}
__device__ __forceinline__ uint32_t smem_u32(const void* p) {
    uint32_t a;
    asm("{ .reg .u64 t; cvta.to.shared.u64 t, %1; cvt.u32.u64 %0, t; }" : "=r"(a) : "l"(p));
    return a;
}
__device__ __forceinline__ void ldsm4(uint32_t* r, uint32_t addr) {
    asm volatile("ldmatrix.sync.aligned.m8n8.x4.shared.b16 {%0,%1,%2,%3}, [%4];"
        : "=r"(r[0]), "=r"(r[1]), "=r"(r[2]), "=r"(r[3]) : "r"(addr));
}
__device__ __forceinline__ void ldsm2(uint32_t* r, uint32_t addr) {
    asm volatile("ldmatrix.sync.aligned.m8n8.x2.shared.b16 {%0,%1}, [%2];"
        : "=r"(r[0]), "=r"(r[1]) : "r"(addr));
}
__device__ __forceinline__ void mma16816(float* c, const uint32_t* a, const uint32_t* b) {
    asm volatile("mma.sync.aligned.m16n8k16.row.col.f32.bf16.bf16.f32 "
        "{%0,%1,%2,%3}, {%4,%5,%6,%7}, {%8,%9}, {%0,%1,%2,%3};"
        : "+f"(c[0]), "+f"(c[1]), "+f"(c[2]), "+f"(c[3])
        : "r"(a[0]), "r"(a[1]), "r"(a[2]), "r"(a[3]), "r"(b[0]), "r"(b[1]));
}
#define CP_A16(dst, src) \
    asm volatile("cp.async.cg.shared.global [%0], [%1], 16;" :: "r"(dst), "l"(src) : "memory")
#define CP_COMMIT() asm volatile("cp.async.commit_group;" ::: "memory")
#define CP_WAIT1()  asm volatile("cp.async.wait_group 1;" ::: "memory")

// ---------------- 1. normalize rows + bf16 split emission ------------------
__global__ void __launch_bounds__(128) normalize_k(
    const float* __restrict__ src, const float* __restrict__ tgt,
    const float* __restrict__ tgt0)
{
    const int r = blockIdx.x;
    const int m = blockIdx.y;
    if (r == 0 && m == 0 && threadIdx.x == 0) g_nc = 0;

    const float* in = (m == 0) ? src : (m == 1) ? tgt : tgt0;

    const float4 v = ((const float4*)(in + (size_t)r * DIM))[threadIdx.x];
    float s = v.x*v.x + v.y*v.y + v.z*v.z + v.w*v.w;
    #pragma unroll
    for (int o = 16; o; o >>= 1) s += __shfl_down_sync(0xffffffffu, s, o);
    __shared__ float ws[4];
    if ((threadIdx.x & 31) == 0) ws[threadIdx.x >> 5] = s;
    __syncthreads();
    const float inv = 1.0f / sqrtf(ws[0] + ws[1] + ws[2] + ws[3]);
    float o4[4] = { v.x * inv, v.y * inv, v.z * inv, v.w * inv };

    __nv_bfloat16 c0[4], c1[4], c2[4];
    #pragma unroll
    for (int t = 0; t < 4; ++t) {
        c0[t] = __float2bfloat16_rn(o4[t]);
        float r1 = o4[t] - __bfloat162float(c0[t]);
        c1[t] = __float2bfloat16_rn(r1);
        c2[t] = __float2bfloat16_rn(r1 - __bfloat162float(c1[t]));
    }
    const int c = threadIdx.x * 4;
    if (m == 0) {            // source S: [b0|b1|b0|b1|b2|b0] and [b0|b1|b0]
        __nv_bfloat16* p = g_TS16 + (size_t)r * KSIM;
        __nv_bfloat16* q = g_B16  + (size_t)r * KSP0;
        #pragma unroll
        for (int t = 0; t < 4; ++t) {
            p[c+t] = c0[t]; p[c+t+512] = c1[t]; p[c+t+1024] = c0[t];
            p[c+t+1536] = c1[t]; p[c+t+2048] = c2[t]; p[c+t+2560] = c0[t];
            q[c+t] = c0[t]; q[c+t+512] = c1[t]; q[c+t+1024] = c0[t];
        }
    } else if (m == 1) {     // target T: [a0|a0|a1|a1|a0|a2]
        __nv_bfloat16* p = g_TT16 + (size_t)r * KSIM;
        #pragma unroll
        for (int t = 0; t < 4; ++t) {
            p[c+t] = c0[t]; p[c+t+512] = c0[t]; p[c+t+1024] = c1[t];
            p[c+t+1536] = c1[t]; p[c+t+2048] = c0[t]; p[c+t+2560] = c2[t];
        }
    } else {                 // T0: [h|h|l]
        __nv_bfloat16* q = g_A16 + (size_t)r * KSP0;
        #pragma unroll
        for (int t = 0; t < 4; ++t) {
            q[c+t] = c0[t]; q[c+t+512] = c0[t]; q[c+t+1024] = c1[t];
        }
    }
}

// ---------------- 2. bf16 mma.sync GEMM  C = A(·,K) @ B(·,K)^T -------------
// 128x128 CTA tile, 8 warps of 64x32, K step 32; 3-stage cp.async pipeline.
// smem stage layout: A 128 rows x 80B @ +0, B 128 rows x 80B @ +10240.
#define ST_BYTES 20480
#define GEMM_SMEM (3 * ST_BYTES)   // 61440
__global__ void __launch_bounds__(256) gemm_bf16(int which, int K)
{
    extern __shared__ char sm[];
    const __nv_bfloat16* __restrict__ A = which ? g_A16 : g_TT16;
    const __nv_bfloat16* __restrict__ B = which ? g_B16 : g_TS16;
    float* __restrict__ C = which ? g_sim0T : g_simT;

    const int tid = threadIdx.x;
    const int bm = blockIdx.y * 128;
    const int bn = blockIdx.x * 128;
    const int lr = tid >> 1;       // row this thread loads
    const int lh = tid & 1;        // k-half: 0 or 16

    const __nv_bfloat16* Ag = A + (size_t)(bm + lr) * K + lh * 16;
    const __nv_bfloat16* Bg = B + (size_t)(bn + lr) * K + lh * 16;

    const uint32_t sbase = smem_u32(sm);
    const uint32_t awr = sbase + (uint32_t)lr * 80u + (uint32_t)lh * 32u;
    const uint32_t bwr = awr + 10240u;

    const int w = tid >> 5, lane = tid & 31;
    const int wm = (w >> 2) * 64;  // 0 / 64
    const int wn = (w & 3) * 32;   // 0 / 32 / 64 / 96
    const uint32_t aoff = (uint32_t)(wm + (lane & 15)) * 80u + (uint32_t)(lane >> 4) * 16u;
    const uint32_t boff = 10240u + (uint32_t)(wn + (lane & 7)) * 80u
                        + (uint32_t)((lane >> 3) & 1) * 16u;

    const int NKT = K >> 5;

    // prologue: prefetch k-tiles 0 and 1
    #pragma unroll
    for (int t = 0; t < 2; ++t) {
        const uint32_t st = (uint32_t)t * ST_BYTES;
        const __nv_bfloat16* as = Ag + t * 32;
        const __nv_bfloat16* bs = Bg + t * 32;
        CP_A16(awr + st, as);
        CP_A16(awr + st + 16u, as + 8);
        CP_A16(bwr + st, bs);
        CP_A16(bwr + st + 16u, bs + 8);
        CP_COMMIT();
    }

    float acc[4][4][4];
    #pragma unroll
    for (int mi = 0; mi < 4; ++mi)
        #pragma unroll
        for (int ni = 0; ni < 4; ++ni)
            #pragma unroll
            for (int t = 0; t < 4; ++t) acc[mi][ni][t] = 0.0f;

    #pragma unroll 1
    for (int kt = 0; kt < NKT; ++kt) {
        CP_WAIT1();
        __syncthreads();                       // stage kt ready for all threads
        if (kt + 2 < NKT) {                    // prefetch kt+2 into stage (kt+2)%3
            const uint32_t st = (uint32_t)((kt + 2) % 3) * ST_BYTES;
            const __nv_bfloat16* as = Ag + (kt + 2) * 32;
            const __nv_bfloat16* bs = Bg + (kt + 2) * 32;
            CP_A16(awr + st, as);
            CP_A16(awr + st + 16u, as + 8);
            CP_A16(bwr + st, bs);
            CP_A16(bwr + st + 16u, bs + 8);
        }
        CP_COMMIT();                           // empty groups keep counts aligned

        const uint32_t st = (uint32_t)(kt % 3) * ST_BYTES;
        const uint32_t abase = sbase + st + aoff;
        const uint32_t bbase = sbase + st + boff;
        #pragma unroll
        for (int kc = 0; kc < 2; ++kc) {
            uint32_t afr[4][4], bfr[4][2];
            #pragma unroll
            for (int mi = 0; mi < 4; ++mi)
                ldsm4(afr[mi], abase + (uint32_t)mi * (16u * 80u) + (uint32_t)kc * 32u);
            #pragma unroll
            for (int ni = 0; ni < 4; ++ni)
                ldsm2(bfr[ni], bbase + (uint32_t)ni * (8u * 80u) + (uint32_t)kc * 32u);
            #pragma unroll
            for (int mi = 0; mi < 4; ++mi)
                #pragma unroll
                for (int ni = 0; ni < 4; ++ni)
                    mma16816(acc[mi][ni], afr[mi], bfr[ni]);
        }
    }

    // epilogue: c0,c1 -> (row, col..col+1); c2,c3 -> (row+8, ...)
    const int rbase = bm + wm + (lane >> 2);
    const int cbase = bn + wn + (lane & 3) * 2;
    #pragma unroll
    for (int mi = 0; mi < 4; ++mi) {
        #pragma unroll
        for (int ni = 0; ni < 4; ++ni) {
            const int rr = rbase + mi * 16;
            const int cc = cbase + ni * 8;
            *(float2*)(C + (size_t)rr * NSRC + cc)       = make_float2(acc[mi][ni][0], acc[mi][ni][1]);
            *(float2*)(C + (size_t)(rr + 8) * NSRC + cc) = make_float2(acc[mi][ni][2], acc[mi][ni][3]);
        }
    }
}

// ---------------- 3. per-target: warp-synchronous selection (unchanged) ----
__global__ void __launch_bounds__(256) rank_kernel(
    const int* __restrict__ slab, const int* __restrict__ tlab)
{
    const int j   = blockIdx.x;
    const int tid = threadIdx.x;
    const int lane = tid & 31;
    const int w    = tid >> 5;

    __shared__ float s_sim0[NSRC];
    __shared__ unsigned char s_lab[NSRC];
    __shared__ unsigned long long s_k10[80];
    __shared__ unsigned long long s_k20[2][160];
    __shared__ int   s_t10[KNN];
    __shared__ int   s_a;
    __shared__ float s_sum[2];

    const float* simrow  = g_simT  + (size_t)j * NSRC;
    const float* sim0row = g_sim0T + (size_t)j * NSRC;

    #pragma unroll
    for (int t = 0; t < 4; ++t) {
        const int i = tid + t * 256;
        ((float4*)s_sim0)[i] = ((const float4*)sim0row)[i];
        int4 lb = ((const int4*)slab)[i];
        uchar4 u;
        u.x = (unsigned char)lb.x; u.y = (unsigned char)lb.y;
        u.z = (unsigned char)lb.z; u.w = (unsigned char)lb.w;
        ((uchar4*)s_lab)[i] = u;
    }

    const int base = w * 512 + lane * 16;
    float v[16];
    {
        const float4* rp = (const float4*)(simrow + base);
        float4 a = rp[0], b = rp[1], c = rp[2], d = rp[3];
        v[0]=a.x; v[1]=a.y; v[2]=a.z;  v[3]=a.w;
        v[4]=b.x; v[5]=b.y; v[6]=b.z;  v[7]=b.w;
        v[8]=c.x; v[9]=c.y; v[10]=c.z; v[11]=c.w;
        v[12]=d.x; v[13]=d.y; v[14]=d.z; v[15]=d.w;
    }

    {
        unsigned int alive = 0xFFFFu;
        #pragma unroll 1
        for (int it = 0; it < KNN; ++it) {
            float best = -INFINITY; int bi = 0;
            #pragma unroll
            for (int i = 0; i < 16; ++i) {
                const float x = ((alive >> i) & 1u) ? v[i] : -INFINITY;
                if (x > best) { best = x; bi = i; }
            }
            unsigned long long key =
                ((unsigned long long)ford(best) << 12) | (unsigned)(4095 - (base + bi));
            key = wmax(key);
            if (lane == 0) s_k10[w * KNN + it] = key;
            const int widx = 4095 - (int)(key & 0xFFFu);
            const unsigned int d = (unsigned)(widx - base);
            if (d < 16u) alive &= ~(1u << d);
        }
    }
    __syncthreads();

    if (w == 0) {
        unsigned long long mk[3];
        mk[0] = s_k10[lane];
        mk[1] = s_k10[lane + 32];
        mk[2] = (lane < 16) ? s_k10[lane + 64] : 0ull;
        unsigned int al = 7u;
        #pragma unroll 1
        for (int it = 0; it < KNN; ++it) {
            unsigned long long b = 0ull;
            #pragma unroll
            for (int t = 0; t < 3; ++t)
                if ((al >> t) & 1u) b = (mk[t] > b) ? mk[t] : b;
            unsigned long long key = wmax(b);
            if (lane == 0) s_t10[it] = 4095 - (int)(key & 0xFFFu);
            #pragma unroll
            for (int t = 0; t < 3; ++t)
                if (mk[t] == key) al &= ~(1u << t);
        }
        if (lane == 0) {
            int cls[KNN];
            #pragma unroll
            for (int k = 0; k < KNN; ++k) cls[k] = s_lab[s_t10[k]];
            int bestc = 1000, bestn = 0;
            #pragma unroll 1
            for (int k = 0; k < KNN; ++k) {
                int n = 0;
                #pragma unroll
                for (int l = 0; l < KNN; ++l) n += (cls[l] == cls[k]);
                if (n > bestn || (n == bestn && cls[k] < bestc)) { bestn = n; bestc = cls[k]; }
            }
            s_a = bestc;
            g_assigned[j] = bestc;
            if (bestc == tlab[j]) atomicAdd(&g_nc, 1);
        }
    }
    __syncthreads();
    const int a = s_a;

    unsigned int inmask = 0u;
    #pragma unroll
    for (int i = 0; i < 16; ++i)
        inmask |= (s_lab[base + i] == a) ? (1u << i) : 0u;

    #pragma unroll 1
    for (int pass = 0; pass < 2; ++pass) {
        unsigned int al = pass ? (0xFFFFu & ~inmask) : inmask;
        int it = 0;
        #pragma unroll 1
        for (; it < RK; ++it) {
            float best = -INFINITY; int bi = 0;
            #pragma unroll
            for (int i = 0; i < 16; ++i) {
                const float x = ((al >> i) & 1u) ? v[i] : -INFINITY;
                if (x > best) { best = x; bi = i; }
            }
            unsigned long long key =
                ((unsigned long long)ford(best) << 12) | (unsigned)(4095 - (base + bi));
            key = wmax(key);
            if ((unsigned)(key >> 12) == FORD_NEGINF) break;
            if (lane == 0) s_k20[pass][w * RK + it] = key;
            const int widx = 4095 - (int)(key & 0xFFFu);
            const unsigned int d = (unsigned)(widx - base);
            if (d < 16u) al &= ~(1u << d);
        }
        for (; it < RK; ++it)
            if (lane == 0) s_k20[pass][w * RK + it] = 0ull;
    }
    __syncthreads();

    if (w < 2) {
        const unsigned long long* keys = s_k20[w];
        unsigned long long mk[5];
        #pragma unroll
        for (int t = 0; t < 5; ++t) mk[t] = keys[lane + 32 * t];
        unsigned int al = 0x1Fu;
        float acc = 0.0f;
        #pragma unroll 1
        for (int it = 0; it < RK; ++it) {
            unsigned long long b = 0ull;
            #pragma unroll
            for (int t = 0; t < 5; ++t)
                if ((al >> t) & 1u) b = (mk[t] > b) ? mk[t] : b;
            unsigned long long key = wmax(b);
            const unsigned int f = (unsigned)(key >> 12);
            if (f == 0u || f == FORD_NEGINF) break;
            acc += s_sim0[4095 - (int)(key & 0xFFFu)];
            #pragma unroll
            for (int t = 0; t < 5; ++t)
                if (mk[t] == key) al &= ~(1u << t);
        }
        if (lane == 0) s_sum[w] = acc;
    }
    __syncthreads();
    if (tid == 0) g_scores[j] = s_sum[0] / s_sum[1];
}

// ---------------- 4. exact top-2048 membership ------------------------------
__global__ void __launch_bounds__(256) select_kernel()
{
    const int j = blockIdx.x;
    const int tid = threadIdx.x;
    __shared__ int sr[8];
    const float sj = g_scores[j];
    int c = 0;
    for (int i = tid; i < NTGT; i += 256) {
        const float si = g_scores[i];
        if (si > sj || (si == sj && i < j)) ++c;
    }
    #pragma unroll
    for (int o = 16; o; o >>= 1) c += __shfl_down_sync(0xffffffffu, c, o);
    if ((tid & 31) == 0) sr[tid >> 5] = c;
    __syncthreads();
    if (tid == 0) {
        int r = 0;
        #pragma unroll
        for (int w = 0; w < 8; ++w) r += sr[w];
        g_sel[j] = (r < TOPN) ? 1 : 0;
    }
}

// ---------------- 5. contrast term per selected column ---------------------
__global__ void __launch_bounds__(256) contrast_kernel(const int* __restrict__ slab)
{
    const int j = blockIdx.x;
    const int tid = threadIdx.x;
    __shared__ float s_m[8];
    __shared__ float s_pA[8];
    __shared__ float s_pM[8];

    if (!g_sel[j]) { if (tid == 0) g_logt[j] = 0.0f; return; }

    const float* row = g_sim0T + (size_t)j * NSRC;
    const int a = g_assigned[j];

    float m = -INFINITY;
    for (int i = tid; i < NSRC; i += 256) m = fmaxf(m, row[i]);
    #pragma unroll
    for (int o = 16; o; o >>= 1) m = fmaxf(m, __shfl_down_sync(0xffffffffu, m, o));
    if ((tid & 31) == 0) s_m[tid >> 5] = m;
    __syncthreads();
    float mm = s_m[0];
    #pragma unroll
    for (int w = 1; w < 8; ++w) mm = fmaxf(mm, s_m[w]);

    float eA = 0.0f, eM = 0.0f;
    const float itau = 1.0f / TAU;
    for (int i = tid; i < NSRC; i += 256) {
        const float e = expf((row[i] - mm) * itau);
        eA += e;
        if (slab[i] == a) eM += e;
    }
    #pragma unroll
    for (int o = 16; o; o >>= 1) {
        eA += __shfl_down_sync(0xffffffffu, eA, o);
        eM += __shfl_down_sync(0xffffffffu, eM, o);
    }
    if ((tid & 31) == 0) { s_pA[tid >> 5] = eA; s_pM[tid >> 5] = eM; }
    __syncthreads();
    if (tid == 0) {
        float tA = 0.0f, tM = 0.0f;
        #pragma unroll
        for (int w = 0; w < 8; ++w) { tA += s_pA[w]; tM += s_pM[w]; }
        g_logt[j] = logf(tM / tA + EPSL);
    }
}

// ---------------- 6. final deterministic reduction --------------------------
__global__ void __launch_bounds__(256) finalize_kernel(float* out, int out_size)
{
    const int tid = threadIdx.x;
    __shared__ float sr[8];
    float acc = 0.0f;
    for (int i = tid; i < NTGT; i += 256) acc += g_logt[i];
    #pragma unroll
    for (int o = 16; o; o >>= 1) acc += __shfl_down_sync(0xffffffffu, acc, o);
    if ((tid & 31) == 0) sr[tid >> 5] = acc;
    __syncthreads();
    if (tid == 0) {
        float tot = 0.0f;
        #pragma unroll
        for (int w = 0; w < 8; ++w) tot += sr[w];
        out[0] = -(tot / (float)TOPN);
        if (out_size > 1) out[1] = (float)g_nc;
    }
}

// ---------------- host launcher ---------------------------------------------
extern "C" void kernel_launch(void* const* d_in, const int* in_sizes, int n_in,
                              void* d_out, int out_size)
{
    const float* src  = (const float*)d_in[0];
    const int*   slab = (const int*)  d_in[1];
    const float* tgt  = (const float*)d_in[2];
    const float* tgt0 = (const float*)d_in[3];
    const int*   tlab = (const int*)  d_in[4];
    float* out = (float*)d_out;

    cudaFuncSetAttribute(gemm_bf16, cudaFuncAttributeMaxDynamicSharedMemorySize,
                         GEMM_SMEM);

    normalize_k<<<dim3(NSRC, 3), 128>>>(src, tgt, tgt0);
    gemm_bf16<<<dim3(32, 32), 256, GEMM_SMEM>>>(0, KSIM);  // simT  (6-term)
    gemm_bf16<<<dim3(32, 32), 256, GEMM_SMEM>>>(1, KSP0);  // sim0T (3-term)
    rank_kernel<<<NTGT, 256>>>(slab, tlab);
    select_kernel<<<NTGT, 256>>>();
    contrast_kernel<<<NTGT, 256>>>(slab);
    finalize_kernel<<<1, 256>>>(out, out_size);
}

// round 9
// speedup vs baseline: 1.3247x; 1.0409x over previous
#include <cuda_runtime.h>
#include <cuda_bf16.h>
#include <math.h>
#include <stdint.h>

#define NSRC 4096
#define NTGT 4096
#define DIM  512
#define KSIM 3072          // 6-term split-K for simT (ordering-only, err ~1e-9)
#define KSP0 1536          // 3-term split-K for sim0T (validated R5)
#define NCLS 64
#define KNN  10
#define RK   20
#define TOPN 2048
#define TAU  0.05f
#define EPSL 1e-6f

#define FORD_NEGINF 0x007FFFFFu

// ---------------- scratch (device globals; allocation-free) ----------------
__device__ __nv_bfloat16 g_TT16[(size_t)NTGT * KSIM];  // T  split [a0|a0|a1|a1|a0|a2]
__device__ __nv_bfloat16 g_TS16[(size_t)NSRC * KSIM];  // S  split [b0|b1|b0|b1|b2|b0]
__device__ __nv_bfloat16 g_A16 [(size_t)NTGT * KSP0];  // T0 split [h|h|l]
__device__ __nv_bfloat16 g_B16 [(size_t)NSRC * KSP0];  // S  split [h|l|h]
__device__ float g_simT [ (size_t)NTGT * NSRC ];
__device__ float g_sim0T[ (size_t)NTGT * NSRC ];
__device__ int   g_assigned[NTGT];
__device__ float g_scores[NTGT];
__device__ int   g_sel[NTGT];
__device__ float g_logt[NTGT];
__device__ int   g_nc;

// ---------------- helpers ---------------------------------------------------
__device__ __forceinline__ unsigned int ford(float f) {
    unsigned int u = __float_as_uint(f);
    return (u & 0x80000000u) ? ~u : (u | 0x80000000u);
}
__device__ __forceinline__ unsigned long long wmax(unsigned long long k) {
    #pragma unroll
    for (int o = 16; o; o >>= 1) {
        unsigned long long t = __shfl_xor_sync(0xffffffffu, k, o);
        if (t > k) k = t;
    }
    return k;
}
__device__ __forceinline__ uint32_t smem_u32(const void* p) {
    uint32_t a;
    asm("{ .reg .u64 t; cvta.to.shared.u64 t, %1; cvt.u32.u64 %0, t; }" : "=r"(a) : "l"(p));
    return a;
}
__device__ __forceinline__ void ldsm4(uint32_t* r, uint32_t addr) {
    asm volatile("ldmatrix.sync.aligned.m8n8.x4.shared.b16 {%0,%1,%2,%3}, [%4];"
        : "=r"(r[0]), "=r"(r[1]), "=r"(r[2]), "=r"(r[3]) : "r"(addr));
}
__device__ __forceinline__ void ldsm2(uint32_t* r, uint32_t addr) {
    asm volatile("ldmatrix.sync.aligned.m8n8.x2.shared.b16 {%0,%1}, [%2];"
        : "=r"(r[0]), "=r"(r[1]) : "r"(addr));
}
__device__ __forceinline__ void mma16816(float* c, const uint32_t* a, const uint32_t* b) {
    asm volatile("mma.sync.aligned.m16n8k16.row.col.f32.bf16.bf16.f32 "
        "{%0,%1,%2,%3}, {%4,%5,%6,%7}, {%8,%9}, {%0,%1,%2,%3};"
        : "+f"(c[0]), "+f"(c[1]), "+f"(c[2]), "+f"(c[3])
        : "r"(a[0]), "r"(a[1]), "r"(a[2]), "r"(a[3]), "r"(b[0]), "r"(b[1]));
}
#define CP_A16(dst, src) \
    asm volatile("cp.async.cg.shared.global [%0], [%1], 16;" :: "r"(dst), "l"(src) : "memory")
#define CP_COMMIT() asm volatile("cp.async.commit_group;" ::: "memory")
#define CP_WAIT1()  asm volatile("cp.async.wait_group 1;" ::: "memory")

// 16-element masked argmax over ordered-uint keys (lowest index wins ties)
__device__ __forceinline__ void scan16(const uint32_t* u, unsigned alive,
                                       uint32_t& best, int& bi) {
    best = 0u; bi = 0;
    #pragma unroll
    for (int i = 0; i < 16; ++i) {
        const uint32_t x = ((alive >> i) & 1u) ? u[i] : 0u;
        if (x > best) { best = x; bi = i; }
    }
}

// ---------------- 1. normalize rows + bf16 split emission ------------------
__global__ void __launch_bounds__(128) normalize_k(
    const float* __restrict__ src, const float* __restrict__ tgt,
    const float* __restrict__ tgt0)
{
    const int r = blockIdx.x;
    const int m = blockIdx.y;
    if (r == 0 && m == 0 && threadIdx.x == 0) g_nc = 0;

    const float* in = (m == 0) ? src : (m == 1) ? tgt : tgt0;

    const float4 v = ((const float4*)(in + (size_t)r * DIM))[threadIdx.x];
    float s = v.x*v.x + v.y*v.y + v.z*v.z + v.w*v.w;
    #pragma unroll
    for (int o = 16; o; o >>= 1) s += __shfl_down_sync(0xffffffffu, s, o);
    __shared__ float ws[4];
    if ((threadIdx.x & 31) == 0) ws[threadIdx.x >> 5] = s;
    __syncthreads();
    const float inv = 1.0f / sqrtf(ws[0] + ws[1] + ws[2] + ws[3]);
    float o4[4] = { v.x * inv, v.y * inv, v.z * inv, v.w * inv };

    __nv_bfloat16 c0[4], c1[4], c2[4];
    #pragma unroll
    for (int t = 0; t < 4; ++t) {
        c0[t] = __float2bfloat16_rn(o4[t]);
        float r1 = o4[t] - __bfloat162float(c0[t]);
        c1[t] = __float2bfloat16_rn(r1);
        c2[t] = __float2bfloat16_rn(r1 - __bfloat162float(c1[t]));
    }
    const int c = threadIdx.x * 4;
    if (m == 0) {            // source S: [b0|b1|b0|b1|b2|b0] and [b0|b1|b0]
        __nv_bfloat16* p = g_TS16 + (size_t)r * KSIM;
        __nv_bfloat16* q = g_B16  + (size_t)r * KSP0;
        #pragma unroll
        for (int t = 0; t < 4; ++t) {
            p[c+t] = c0[t]; p[c+t+512] = c1[t]; p[c+t+1024] = c0[t];
            p[c+t+1536] = c1[t]; p[c+t+2048] = c2[t]; p[c+t+2560] = c0[t];
            q[c+t] = c0[t]; q[c+t+512] = c1[t]; q[c+t+1024] = c0[t];
        }
    } else if (m == 1) {     // target T: [a0|a0|a1|a1|a0|a2]
        __nv_bfloat16* p = g_TT16 + (size_t)r * KSIM;
        #pragma unroll
        for (int t = 0; t < 4; ++t) {
            p[c+t] = c0[t]; p[c+t+512] = c0[t]; p[c+t+1024] = c1[t];
            p[c+t+1536] = c1[t]; p[c+t+2048] = c0[t]; p[c+t+2560] = c2[t];
        }
    } else {                 // T0: [h|h|l]
        __nv_bfloat16* q = g_A16 + (size_t)r * KSP0;
        #pragma unroll
        for (int t = 0; t < 4; ++t) {
            q[c+t] = c0[t]; q[c+t+512] = c0[t]; q[c+t+1024] = c1[t];
        }
    }
}

// ---------------- 2. bf16 mma.sync GEMM (unchanged from R8) ----------------
#define ST_BYTES 20480
#define GEMM_SMEM (3 * ST_BYTES)   // 61440
__global__ void __launch_bounds__(256) gemm_bf16(int which, int K)
{
    extern __shared__ char sm[];
    const __nv_bfloat16* __restrict__ A = which ? g_A16 : g_TT16;
    const __nv_bfloat16* __restrict__ B = which ? g_B16 : g_TS16;
    float* __restrict__ C = which ? g_sim0T : g_simT;

    const int tid = threadIdx.x;
    const int bm = blockIdx.y * 128;
    const int bn = blockIdx.x * 128;
    const int lr = tid >> 1;
    const int lh = tid & 1;

    const __nv_bfloat16* Ag = A + (size_t)(bm + lr) * K + lh * 16;
    const __nv_bfloat16* Bg = B + (size_t)(bn + lr) * K + lh * 16;

    const uint32_t sbase = smem_u32(sm);
    const uint32_t awr = sbase + (uint32_t)lr * 80u + (uint32_t)lh * 32u;
    const uint32_t bwr = awr + 10240u;

    const int w = tid >> 5, lane = tid & 31;
    const int wm = (w >> 2) * 64;
    const int wn = (w & 3) * 32;
    const uint32_t aoff = (uint32_t)(wm + (lane & 15)) * 80u + (uint32_t)(lane >> 4) * 16u;
    const uint32_t boff = 10240u + (uint32_t)(wn + (lane & 7)) * 80u
                        + (uint32_t)((lane >> 3) & 1) * 16u;

    const int NKT = K >> 5;

    #pragma unroll
    for (int t = 0; t < 2; ++t) {
        const uint32_t st = (uint32_t)t * ST_BYTES;
        const __nv_bfloat16* as = Ag + t * 32;
        const __nv_bfloat16* bs = Bg + t * 32;
        CP_A16(awr + st, as);
        CP_A16(awr + st + 16u, as + 8);
        CP_A16(bwr + st, bs);
        CP_A16(bwr + st + 16u, bs + 8);
        CP_COMMIT();
    }

    float acc[4][4][4];
    #pragma unroll
    for (int mi = 0; mi < 4; ++mi)
        #pragma unroll
        for (int ni = 0; ni < 4; ++ni)
            #pragma unroll
            for (int t = 0; t < 4; ++t) acc[mi][ni][t] = 0.0f;

    #pragma unroll 1
    for (int kt = 0; kt < NKT; ++kt) {
        CP_WAIT1();
        __syncthreads();
        if (kt + 2 < NKT) {
            const uint32_t st = (uint32_t)((kt + 2) % 3) * ST_BYTES;
            const __nv_bfloat16* as = Ag + (kt + 2) * 32;
            const __nv_bfloat16* bs = Bg + (kt + 2) * 32;
            CP_A16(awr + st, as);
            CP_A16(awr + st + 16u, as + 8);
            CP_A16(bwr + st, bs);
            CP_A16(bwr + st + 16u, bs + 8);
        }
        CP_COMMIT();

        const uint32_t st = (uint32_t)(kt % 3) * ST_BYTES;
        const uint32_t abase = sbase + st + aoff;
        const uint32_t bbase = sbase + st + boff;
        #pragma unroll
        for (int kc = 0; kc < 2; ++kc) {
            uint32_t afr[4][4], bfr[4][2];
            #pragma unroll
            for (int mi = 0; mi < 4; ++mi)
                ldsm4(afr[mi], abase + (uint32_t)mi * (16u * 80u) + (uint32_t)kc * 32u);
            #pragma unroll
            for (int ni = 0; ni < 4; ++ni)
                ldsm2(bfr[ni], bbase + (uint32_t)ni * (8u * 80u) + (uint32_t)kc * 32u);
            #pragma unroll
            for (int mi = 0; mi < 4; ++mi)
                #pragma unroll
                for (int ni = 0; ni < 4; ++ni)
                    mma16816(acc[mi][ni], afr[mi], bfr[ni]);
        }
    }

    const int rbase = bm + wm + (lane >> 2);
    const int cbase = bn + wn + (lane & 3) * 2;
    #pragma unroll
    for (int mi = 0; mi < 4; ++mi) {
        #pragma unroll
        for (int ni = 0; ni < 4; ++ni) {
            const int rr = rbase + mi * 16;
            const int cc = cbase + ni * 8;
            *(float2*)(C + (size_t)rr * NSRC + cc)       = make_float2(acc[mi][ni][0], acc[mi][ni][1]);
            *(float2*)(C + (size_t)(rr + 8) * NSRC + cc) = make_float2(acc[mi][ni][2], acc[mi][ni][3]);
        }
    }
}

// ---------------- 3. per-target selection: redux + cached-argmax -----------
// Semantics identical to jnp stable argsort (val desc, idx asc):
//  - keys are ordered-uint ford(sim); 32-bit warp redux finds the max;
//  - ballot + ffs picks the lowest lane (= lowest global index, lane-major);
//  - within a thread, scan16 picks the lowest element index;
//  - only the winning lane rescans its 16 registers (cached argmax).
__global__ void __launch_bounds__(256) rank_kernel(
    const int* __restrict__ slab, const int* __restrict__ tlab)
{
    const int j   = blockIdx.x;
    const int tid = threadIdx.x;
    const int lane = tid & 31;
    const int w    = tid >> 5;

    __shared__ float s_sim0[NSRC];
    __shared__ unsigned char s_lab[NSRC];
    __shared__ unsigned long long s_k10[80];
    __shared__ unsigned long long s_k20[2][160];
    __shared__ int   s_t10[KNN];
    __shared__ int   s_a;
    __shared__ float s_sum[2];

    const float* simrow  = g_simT  + (size_t)j * NSRC;
    const float* sim0row = g_sim0T + (size_t)j * NSRC;

    #pragma unroll
    for (int t = 0; t < 4; ++t) {
        const int i = tid + t * 256;
        ((float4*)s_sim0)[i] = ((const float4*)sim0row)[i];
        int4 lb = ((const int4*)slab)[i];
        uchar4 uu;
        uu.x = (unsigned char)lb.x; uu.y = (unsigned char)lb.y;
        uu.z = (unsigned char)lb.z; uu.w = (unsigned char)lb.w;
        ((uchar4*)s_lab)[i] = uu;
    }

    const int base = w * 512 + lane * 16;
    uint32_t u[16];
    {
        const float4* rp = (const float4*)(simrow + base);
        float4 a = rp[0], b = rp[1], c = rp[2], d = rp[3];
        u[0]=ford(a.x);  u[1]=ford(a.y);  u[2]=ford(a.z);  u[3]=ford(a.w);
        u[4]=ford(b.x);  u[5]=ford(b.y);  u[6]=ford(b.z);  u[7]=ford(b.w);
        u[8]=ford(c.x);  u[9]=ford(c.y);  u[10]=ford(c.z); u[11]=ford(c.w);
        u[12]=ford(d.x); u[13]=ford(d.y); u[14]=ford(d.z); u[15]=ford(d.w);
    }

    // ---- per-warp top-10 overall ----
    {
        unsigned alive = 0xFFFFu;
        uint32_t best; int bi;
        scan16(u, alive, best, bi);
        #pragma unroll 1
        for (int it = 0; it < KNN; ++it) {
            const uint32_t m = __reduce_max_sync(0xffffffffu, best);
            const unsigned msk = __ballot_sync(0xffffffffu, best == m);
            const int src = __ffs(msk) - 1;
            const int widx = __shfl_sync(0xffffffffu, base + bi, src);
            if (lane == 0)
                s_k10[w * KNN + it] =
                    ((unsigned long long)m << 12) | (unsigned)(4095 - widx);
            if (lane == src) {
                alive &= ~(1u << bi);
                scan16(u, alive, best, bi);
            }
        }
    }
    __syncthreads();

    // ---- warp 0: merge 80 candidates -> global top-10, assign label ----
    if (w == 0) {
        unsigned long long mk[3];
        mk[0] = s_k10[lane];
        mk[1] = s_k10[lane + 32];
        mk[2] = (lane < 16) ? s_k10[lane + 64] : 0ull;
        unsigned int al = 7u;
        #pragma unroll 1
        for (int it = 0; it < KNN; ++it) {
            unsigned long long b = 0ull;
            #pragma unroll
            for (int t = 0; t < 3; ++t)
                if ((al >> t) & 1u) b = (mk[t] > b) ? mk[t] : b;
            unsigned long long key = wmax(b);
            if (lane == 0) s_t10[it] = 4095 - (int)(key & 0xFFFu);
            #pragma unroll
            for (int t = 0; t < 3; ++t)
                if (mk[t] == key) al &= ~(1u << t);
        }
        if (lane == 0) {
            int cls[KNN];
            #pragma unroll
            for (int k = 0; k < KNN; ++k) cls[k] = s_lab[s_t10[k]];
            int bestc = 1000, bestn = 0;
            #pragma unroll 1
            for (int k = 0; k < KNN; ++k) {
                int n = 0;
                #pragma unroll
                for (int l = 0; l < KNN; ++l) n += (cls[l] == cls[k]);
                if (n > bestn || (n == bestn && cls[k] < bestc)) { bestn = n; bestc = cls[k]; }
            }
            s_a = bestc;
            g_assigned[j] = bestc;
            if (bestc == tlab[j]) atomicAdd(&g_nc, 1);
        }
    }
    __syncthreads();
    const int a = s_a;

    // ---- per-warp masked top-20 candidates (in-class / out-of-class) ----
    unsigned int inmask = 0u;
    #pragma unroll
    for (int i = 0; i < 16; ++i)
        inmask |= (s_lab[base + i] == a) ? (1u << i) : 0u;

    #pragma unroll 1
    for (int pass = 0; pass < 2; ++pass) {
        unsigned al = pass ? (0xFFFFu & ~inmask) : inmask;
        uint32_t best; int bi;
        scan16(u, al, best, bi);
        int it = 0;
        #pragma unroll 1
        for (; it < RK; ++it) {
            const uint32_t m = __reduce_max_sync(0xffffffffu, best);
            if (m == 0u) break;                       // warp exhausted
            const unsigned msk = __ballot_sync(0xffffffffu, best == m);
            const int src = __ffs(msk) - 1;
            const int widx = __shfl_sync(0xffffffffu, base + bi, src);
            if (lane == 0)
                s_k20[pass][w * RK + it] =
                    ((unsigned long long)m << 12) | (unsigned)(4095 - widx);
            if (lane == src) {
                al &= ~(1u << bi);
                scan16(u, al, best, bi);
            }
        }
        for (; it < RK; ++it)
            if (lane == 0) s_k20[pass][w * RK + it] = 0ull;
    }
    __syncthreads();

    // ---- warps 0,1 concurrently merge the two 160-candidate lists ----
    if (w < 2) {
        const unsigned long long* keys = s_k20[w];
        unsigned long long mk[5];
        #pragma unroll
        for (int t = 0; t < 5; ++t) mk[t] = keys[lane + 32 * t];
        unsigned int al = 0x1Fu;
        float acc = 0.0f;
        #pragma unroll 1
        for (int it = 0; it < RK; ++it) {
            unsigned long long b = 0ull;
            #pragma unroll
            for (int t = 0; t < 5; ++t)
                if ((al >> t) & 1u) b = (mk[t] > b) ? mk[t] : b;
            unsigned long long key = wmax(b);
            const unsigned int f = (unsigned)(key >> 12);
            if (f == 0u || f == FORD_NEGINF) break;
            acc += s_sim0[4095 - (int)(key & 0xFFFu)];
            #pragma unroll
            for (int t = 0; t < 5; ++t)
                if (mk[t] == key) al &= ~(1u << t);
        }
        if (lane == 0) s_sum[w] = acc;
    }
    __syncthreads();
    if (tid == 0) g_scores[j] = s_sum[0] / s_sum[1];
}

// ---------------- 4. exact top-2048 membership ------------------------------
__global__ void __launch_bounds__(256) select_kernel()
{
    const int j = blockIdx.x;
    const int tid = threadIdx.x;
    __shared__ int sr[8];
    const float sj = g_scores[j];
    int c = 0;
    for (int i = tid; i < NTGT; i += 256) {
        const float si = g_scores[i];
        if (si > sj || (si == sj && i < j)) ++c;
    }
    #pragma unroll
    for (int o = 16; o; o >>= 1) c += __shfl_down_sync(0xffffffffu, c, o);
    if ((tid & 31) == 0) sr[tid >> 5] = c;
    __syncthreads();
    if (tid == 0) {
        int r = 0;
        #pragma unroll
        for (int w = 0; w < 8; ++w) r += sr[w];
        g_sel[j] = (r < TOPN) ? 1 : 0;
    }
}

// ---------------- 5. contrast term per selected column ---------------------
__global__ void __launch_bounds__(256) contrast_kernel(const int* __restrict__ slab)
{
    const int j = blockIdx.x;
    const int tid = threadIdx.x;
    __shared__ float s_m[8];
    __shared__ float s_pA[8];
    __shared__ float s_pM[8];

    if (!g_sel[j]) { if (tid == 0) g_logt[j] = 0.0f; return; }

    const float* row = g_sim0T + (size_t)j * NSRC;
    const int a = g_assigned[j];

    float m = -INFINITY;
    for (int i = tid; i < NSRC; i += 256) m = fmaxf(m, row[i]);
    #pragma unroll
    for (int o = 16; o; o >>= 1) m = fmaxf(m, __shfl_down_sync(0xffffffffu, m, o));
    if ((tid & 31) == 0) s_m[tid >> 5] = m;
    __syncthreads();
    float mm = s_m[0];
    #pragma unroll
    for (int w = 1; w < 8; ++w) mm = fmaxf(mm, s_m[w]);

    float eA = 0.0f, eM = 0.0f;
    const float itau = 1.0f / TAU;
    for (int i = tid; i < NSRC; i += 256) {
        const float e = expf((row[i] - mm) * itau);
        eA += e;
        if (slab[i] == a) eM += e;
    }
    #pragma unroll
    for (int o = 16; o; o >>= 1) {
        eA += __shfl_down_sync(0xffffffffu, eA, o);
        eM += __shfl_down_sync(0xffffffffu, eM, o);
    }
    if ((tid & 31) == 0) { s_pA[tid >> 5] = eA; s_pM[tid >> 5] = eM; }
    __syncthreads();
    if (tid == 0) {
        float tA = 0.0f, tM = 0.0f;
        #pragma unroll
        for (int w = 0; w < 8; ++w) { tA += s_pA[w]; tM += s_pM[w]; }
        g_logt[j] = logf(tM / tA + EPSL);
    }
}

// ---------------- 6. final deterministic reduction --------------------------
__global__ void __launch_bounds__(256) finalize_kernel(float* out, int out_size)
{
    const int tid = threadIdx.x;
    __shared__ float sr[8];
    float acc = 0.0f;
    for (int i = tid; i < NTGT; i += 256) acc += g_logt[i];
    #pragma unroll
    for (int o = 16; o; o >>= 1) acc += __shfl_down_sync(0xffffffffu, acc, o);
    if ((tid & 31) == 0) sr[tid >> 5] = acc;
    __syncthreads();
    if (tid == 0) {
        float tot = 0.0f;
        #pragma unroll
        for (int w = 0; w < 8; ++w) tot += sr[w];
        out[0] = -(tot / (float)TOPN);
        if (out_size > 1) out[1] = (float)g_nc;
    }
}

// ---------------- host launcher ---------------------------------------------
extern "C" void kernel_launch(void* const* d_in, const int* in_sizes, int n_in,
                              void* d_out, int out_size)
{
    const float* src  = (const float*)d_in[0];
    const int*   slab = (const int*)  d_in[1];
    const float* tgt  = (const float*)d_in[2];
    const float* tgt0 = (const float*)d_in[3];
    const int*   tlab = (const int*)  d_in[4];
    float* out = (float*)d_out;

    cudaFuncSetAttribute(gemm_bf16, cudaFuncAttributeMaxDynamicSharedMemorySize,
                         GEMM_SMEM);

    normalize_k<<<dim3(NSRC, 3), 128>>>(src, tgt, tgt0);
    gemm_bf16<<<dim3(32, 32), 256, GEMM_SMEM>>>(0, KSIM);  // simT  (6-term)
    gemm_bf16<<<dim3(32, 32), 256, GEMM_SMEM>>>(1, KSP0);  // sim0T (3-term)
    rank_kernel<<<NTGT, 256>>>(slab, tlab);
    select_kernel<<<NTGT, 256>>>();
    contrast_kernel<<<NTGT, 256>>>(slab);
    finalize_kernel<<<1, 256>>>(out, out_size);
}

// round 10
// speedup vs baseline: 1.7208x; 1.2990x over previous
#include <cuda_runtime.h>
#include <cuda_fp16.h>
#include <math.h>
#include <stdint.h>

#define NSRC 4096
#define NTGT 4096
#define DIM  512
#define KSPL 1536          // 3-product fp16 split-K (err ~1e-8, = fp32 baseline)
#define NCLS 64
#define KNN  10
#define RK   20
#define TOPN 2048
#define TAU  0.05f
#define EPSL 1e-6f

#define FORD_NEGINF 0x007FFFFFu

// ---------------- scratch (device globals; allocation-free) ----------------
__device__ __half g_T16 [(size_t)NTGT * KSPL];  // T  split [a0|a0|a1]
__device__ __half g_T016[(size_t)NTGT * KSPL];  // T0 split [a0|a0|a1]
__device__ __half g_S16 [(size_t)NSRC * KSPL];  // S  split [b0|b1|b0] (shared B)
__device__ float g_simT [ (size_t)NTGT * NSRC ];
__device__ float g_sim0T[ (size_t)NTGT * NSRC ];
__device__ int   g_assigned[NTGT];
__device__ float g_scores[NTGT];
__device__ int   g_sel[NTGT];
__device__ float g_logt[NTGT];
__device__ int   g_nc;

// ---------------- helpers ---------------------------------------------------
__device__ __forceinline__ unsigned int ford(float f) {
    unsigned int u = __float_as_uint(f);
    return (u & 0x80000000u) ? ~u : (u | 0x80000000u);
}
__device__ __forceinline__ unsigned long long wmax(unsigned long long k) {
    #pragma unroll
    for (int o = 16; o; o >>= 1) {
        unsigned long long t = __shfl_xor_sync(0xffffffffu, k, o);
        if (t > k) k = t;
    }
    return k;
}
__device__ __forceinline__ uint32_t smem_u32(const void* p) {
    uint32_t a;
    asm("{ .reg .u64 t; cvta.to.shared.u64 t, %1; cvt.u32.u64 %0, t; }" : "=r"(a) : "l"(p));
    return a;
}
__device__ __forceinline__ void ldsm4(uint32_t* r, uint32_t addr) {
    asm volatile("ldmatrix.sync.aligned.m8n8.x4.shared.b16 {%0,%1,%2,%3}, [%4];"
        : "=r"(r[0]), "=r"(r[1]), "=r"(r[2]), "=r"(r[3]) : "r"(addr));
}
__device__ __forceinline__ void ldsm2(uint32_t* r, uint32_t addr) {
    asm volatile("ldmatrix.sync.aligned.m8n8.x2.shared.b16 {%0,%1}, [%2];"
        : "=r"(r[0]), "=r"(r[1]) : "r"(addr));
}
__device__ __forceinline__ void mma16816(float* c, const uint32_t* a, const uint32_t* b) {
    asm volatile("mma.sync.aligned.m16n8k16.row.col.f32.f16.f16.f32 "
        "{%0,%1,%2,%3}, {%4,%5,%6,%7}, {%8,%9}, {%0,%1,%2,%3};"
        : "+f"(c[0]), "+f"(c[1]), "+f"(c[2]), "+f"(c[3])
        : "r"(a[0]), "r"(a[1]), "r"(a[2]), "r"(a[3]), "r"(b[0]), "r"(b[1]));
}
#define CP_A16(dst, src) \
    asm volatile("cp.async.cg.shared.global [%0], [%1], 16;" :: "r"(dst), "l"(src) : "memory")
#define CP_COMMIT() asm volatile("cp.async.commit_group;" ::: "memory")
#define CP_WAIT1()  asm volatile("cp.async.wait_group 1;" ::: "memory")

// 16-element masked argmax over ordered-uint keys (lowest index wins ties)
__device__ __forceinline__ void scan16(const uint32_t* u, unsigned alive,
                                       uint32_t& best, int& bi) {
    best = 0u; bi = 0;
    #pragma unroll
    for (int i = 0; i < 16; ++i) {
        const uint32_t x = ((alive >> i) & 1u) ? u[i] : 0u;
        if (x > best) { best = x; bi = i; }
    }
}

// ---------------- 1. normalize rows + fp16 2-component split emission ------
__global__ void __launch_bounds__(128) normalize_k(
    const float* __restrict__ src, const float* __restrict__ tgt,
    const float* __restrict__ tgt0)
{
    const int r = blockIdx.x;
    const int m = blockIdx.y;
    if (r == 0 && m == 0 && threadIdx.x == 0) g_nc = 0;

    const float* in = (m == 0) ? src : (m == 1) ? tgt : tgt0;

    const float4 v = ((const float4*)(in + (size_t)r * DIM))[threadIdx.x];
    float s = v.x*v.x + v.y*v.y + v.z*v.z + v.w*v.w;
    #pragma unroll
    for (int o = 16; o; o >>= 1) s += __shfl_down_sync(0xffffffffu, s, o);
    __shared__ float ws[4];
    if ((threadIdx.x & 31) == 0) ws[threadIdx.x >> 5] = s;
    __syncthreads();
    const float inv = 1.0f / sqrtf(ws[0] + ws[1] + ws[2] + ws[3]);
    float o4[4] = { v.x * inv, v.y * inv, v.z * inv, v.w * inv };

    __half c0[4], c1[4];
    #pragma unroll
    for (int t = 0; t < 4; ++t) {
        c0[t] = __float2half_rn(o4[t]);
        c1[t] = __float2half_rn(o4[t] - __half2float(c0[t]));
    }
    const int c = threadIdx.x * 4;
    if (m == 0) {            // source S (shared B): [b0 | b1 | b0]
        __half* p = g_S16 + (size_t)r * KSPL;
        #pragma unroll
        for (int t = 0; t < 4; ++t) {
            p[c+t] = c0[t]; p[c+t+512] = c1[t]; p[c+t+1024] = c0[t];
        }
    } else {                 // T / T0: [a0 | a0 | a1]
        __half* p = ((m == 1) ? g_T16 : g_T016) + (size_t)r * KSPL;
        #pragma unroll
        for (int t = 0; t < 4; ++t) {
            p[c+t] = c0[t]; p[c+t+512] = c0[t]; p[c+t+1024] = c1[t];
        }
    }
}

// ---------------- 2. fp16 mma.sync GEMM (R8-validated data path) -----------
#define ST_BYTES 20480
#define GEMM_SMEM (3 * ST_BYTES)   // 61440
__global__ void __launch_bounds__(256) gemm_f16(int which, int K)
{
    extern __shared__ char sm[];
    const __half* __restrict__ A = which ? g_T016 : g_T16;
    const __half* __restrict__ B = g_S16;
    float* __restrict__ C = which ? g_sim0T : g_simT;

    const int tid = threadIdx.x;
    const int bm = blockIdx.y * 128;
    const int bn = blockIdx.x * 128;
    const int lr = tid >> 1;
    const int lh = tid & 1;

    const __half* Ag = A + (size_t)(bm + lr) * K + lh * 16;
    const __half* Bg = B + (size_t)(bn + lr) * K + lh * 16;

    const uint32_t sbase = smem_u32(sm);
    const uint32_t awr = sbase + (uint32_t)lr * 80u + (uint32_t)lh * 32u;
    const uint32_t bwr = awr + 10240u;

    const int w = tid >> 5, lane = tid & 31;
    const int wm = (w >> 2) * 64;
    const int wn = (w & 3) * 32;
    const uint32_t aoff = (uint32_t)(wm + (lane & 15)) * 80u + (uint32_t)(lane >> 4) * 16u;
    const uint32_t boff = 10240u + (uint32_t)(wn + (lane & 7)) * 80u
                        + (uint32_t)((lane >> 3) & 1) * 16u;

    const int NKT = K >> 5;

    #pragma unroll
    for (int t = 0; t < 2; ++t) {
        const uint32_t st = (uint32_t)t * ST_BYTES;
        const __half* as = Ag + t * 32;
        const __half* bs = Bg + t * 32;
        CP_A16(awr + st, as);
        CP_A16(awr + st + 16u, as + 8);
        CP_A16(bwr + st, bs);
        CP_A16(bwr + st + 16u, bs + 8);
        CP_COMMIT();
    }

    float acc[4][4][4];
    #pragma unroll
    for (int mi = 0; mi < 4; ++mi)
        #pragma unroll
        for (int ni = 0; ni < 4; ++ni)
            #pragma unroll
            for (int t = 0; t < 4; ++t) acc[mi][ni][t] = 0.0f;

    #pragma unroll 1
    for (int kt = 0; kt < NKT; ++kt) {
        CP_WAIT1();
        __syncthreads();
        if (kt + 2 < NKT) {
            const uint32_t st = (uint32_t)((kt + 2) % 3) * ST_BYTES;
            const __half* as = Ag + (kt + 2) * 32;
            const __half* bs = Bg + (kt + 2) * 32;
            CP_A16(awr + st, as);
            CP_A16(awr + st + 16u, as + 8);
            CP_A16(bwr + st, bs);
            CP_A16(bwr + st + 16u, bs + 8);
        }
        CP_COMMIT();

        const uint32_t st = (uint32_t)(kt % 3) * ST_BYTES;
        const uint32_t abase = sbase + st + aoff;
        const uint32_t bbase = sbase + st + boff;
        #pragma unroll
        for (int kc = 0; kc < 2; ++kc) {
            uint32_t afr[4][4], bfr[4][2];
            #pragma unroll
            for (int mi = 0; mi < 4; ++mi)
                ldsm4(afr[mi], abase + (uint32_t)mi * (16u * 80u) + (uint32_t)kc * 32u);
            #pragma unroll
            for (int ni = 0; ni < 4; ++ni)
                ldsm2(bfr[ni], bbase + (uint32_t)ni * (8u * 80u) + (uint32_t)kc * 32u);
            #pragma unroll
            for (int mi = 0; mi < 4; ++mi)
                #pragma unroll
                for (int ni = 0; ni < 4; ++ni)
                    mma16816(acc[mi][ni], afr[mi], bfr[ni]);
        }
    }

    const int rbase = bm + wm + (lane >> 2);
    const int cbase = bn + wn + (lane & 3) * 2;
    #pragma unroll
    for (int mi = 0; mi < 4; ++mi) {
        #pragma unroll
        for (int ni = 0; ni < 4; ++ni) {
            const int rr = rbase + mi * 16;
            const int cc = cbase + ni * 8;
            *(float2*)(C + (size_t)rr * NSRC + cc)       = make_float2(acc[mi][ni][0], acc[mi][ni][1]);
            *(float2*)(C + (size_t)(rr + 8) * NSRC + cc) = make_float2(acc[mi][ni][2], acc[mi][ni][3]);
        }
    }
}

// ---------------- 3. per-target selection (unchanged from R9) --------------
__global__ void __launch_bounds__(256) rank_kernel(
    const int* __restrict__ slab, const int* __restrict__ tlab)
{
    const int j   = blockIdx.x;
    const int tid = threadIdx.x;
    const int lane = tid & 31;
    const int w    = tid >> 5;

    __shared__ float s_sim0[NSRC];
    __shared__ unsigned char s_lab[NSRC];
    __shared__ unsigned long long s_k10[80];
    __shared__ unsigned long long s_k20[2][160];
    __shared__ int   s_t10[KNN];
    __shared__ int   s_a;
    __shared__ float s_sum[2];

    const float* simrow  = g_simT  + (size_t)j * NSRC;
    const float* sim0row = g_sim0T + (size_t)j * NSRC;

    #pragma unroll
    for (int t = 0; t < 4; ++t) {
        const int i = tid + t * 256;
        ((float4*)s_sim0)[i] = ((const float4*)sim0row)[i];
        int4 lb = ((const int4*)slab)[i];
        uchar4 uu;
        uu.x = (unsigned char)lb.x; uu.y = (unsigned char)lb.y;
        uu.z = (unsigned char)lb.z; uu.w = (unsigned char)lb.w;
        ((uchar4*)s_lab)[i] = uu;
    }

    const int base = w * 512 + lane * 16;
    uint32_t u[16];
    {
        const float4* rp = (const float4*)(simrow + base);
        float4 a = rp[0], b = rp[1], c = rp[2], d = rp[3];
        u[0]=ford(a.x);  u[1]=ford(a.y);  u[2]=ford(a.z);  u[3]=ford(a.w);
        u[4]=ford(b.x);  u[5]=ford(b.y);  u[6]=ford(b.z);  u[7]=ford(b.w);
        u[8]=ford(c.x);  u[9]=ford(c.y);  u[10]=ford(c.z); u[11]=ford(c.w);
        u[12]=ford(d.x); u[13]=ford(d.y); u[14]=ford(d.z); u[15]=ford(d.w);
    }

    {
        unsigned alive = 0xFFFFu;
        uint32_t best; int bi;
        scan16(u, alive, best, bi);
        #pragma unroll 1
        for (int it = 0; it < KNN; ++it) {
            const uint32_t m = __reduce_max_sync(0xffffffffu, best);
            const unsigned msk = __ballot_sync(0xffffffffu, best == m);
            const int src = __ffs(msk) - 1;
            const int widx = __shfl_sync(0xffffffffu, base + bi, src);
            if (lane == 0)
                s_k10[w * KNN + it] =
                    ((unsigned long long)m << 12) | (unsigned)(4095 - widx);
            if (lane == src) {
                alive &= ~(1u << bi);
                scan16(u, alive, best, bi);
            }
        }
    }
    __syncthreads();

    if (w == 0) {
        unsigned long long mk[3];
        mk[0] = s_k10[lane];
        mk[1] = s_k10[lane + 32];
        mk[2] = (lane < 16) ? s_k10[lane + 64] : 0ull;
        unsigned int al = 7u;
        #pragma unroll 1
        for (int it = 0; it < KNN; ++it) {
            unsigned long long b = 0ull;
            #pragma unroll
            for (int t = 0; t < 3; ++t)
                if ((al >> t) & 1u) b = (mk[t] > b) ? mk[t] : b;
            unsigned long long key = wmax(b);
            if (lane == 0) s_t10[it] = 4095 - (int)(key & 0xFFFu);
            #pragma unroll
            for (int t = 0; t < 3; ++t)
                if (mk[t] == key) al &= ~(1u << t);
        }
        if (lane == 0) {
            int cls[KNN];
            #pragma unroll
            for (int k = 0; k < KNN; ++k) cls[k] = s_lab[s_t10[k]];
            int bestc = 1000, bestn = 0;
            #pragma unroll 1
            for (int k = 0; k < KNN; ++k) {
                int n = 0;
                #pragma unroll
                for (int l = 0; l < KNN; ++l) n += (cls[l] == cls[k]);
                if (n > bestn || (n == bestn && cls[k] < bestc)) { bestn = n; bestc = cls[k]; }
            }
            s_a = bestc;
            g_assigned[j] = bestc;
            if (bestc == tlab[j]) atomicAdd(&g_nc, 1);
        }
    }
    __syncthreads();
    const int a = s_a;

    unsigned int inmask = 0u;
    #pragma unroll
    for (int i = 0; i < 16; ++i)
        inmask |= (s_lab[base + i] == a) ? (1u << i) : 0u;

    #pragma unroll 1
    for (int pass = 0; pass < 2; ++pass) {
        unsigned al = pass ? (0xFFFFu & ~inmask) : inmask;
        uint32_t best; int bi;
        scan16(u, al, best, bi);
        int it = 0;
        #pragma unroll 1
        for (; it < RK; ++it) {
            const uint32_t m = __reduce_max_sync(0xffffffffu, best);
            if (m == 0u) break;
            const unsigned msk = __ballot_sync(0xffffffffu, best == m);
            const int src = __ffs(msk) - 1;
            const int widx = __shfl_sync(0xffffffffu, base + bi, src);
            if (lane == 0)
                s_k20[pass][w * RK + it] =
                    ((unsigned long long)m << 12) | (unsigned)(4095 - widx);
            if (lane == src) {
                al &= ~(1u << bi);
                scan16(u, al, best, bi);
            }
        }
        for (; it < RK; ++it)
            if (lane == 0) s_k20[pass][w * RK + it] = 0ull;
    }
    __syncthreads();

    if (w < 2) {
        const unsigned long long* keys = s_k20[w];
        unsigned long long mk[5];
        #pragma unroll
        for (int t = 0; t < 5; ++t) mk[t] = keys[lane + 32 * t];
        unsigned int al = 0x1Fu;
        float acc = 0.0f;
        #pragma unroll 1
        for (int it = 0; it < RK; ++it) {
            unsigned long long b = 0ull;
            #pragma unroll
            for (int t = 0; t < 5; ++t)
                if ((al >> t) & 1u) b = (mk[t] > b) ? mk[t] : b;
            unsigned long long key = wmax(b);
            const unsigned int f = (unsigned)(key >> 12);
            if (f == 0u || f == FORD_NEGINF) break;
            acc += s_sim0[4095 - (int)(key & 0xFFFu)];
            #pragma unroll
            for (int t = 0; t < 5; ++t)
                if (mk[t] == key) al &= ~(1u << t);
        }
        if (lane == 0) s_sum[w] = acc;
    }
    __syncthreads();
    if (tid == 0) g_scores[j] = s_sum[0] / s_sum[1];
}

// ---------------- 4. exact top-2048 membership ------------------------------
__global__ void __launch_bounds__(256) select_kernel()
{
    const int j = blockIdx.x;
    const int tid = threadIdx.x;
    __shared__ int sr[8];
    const float sj = g_scores[j];
    int c = 0;
    for (int i = tid; i < NTGT; i += 256) {
        const float si = g_scores[i];
        if (si > sj || (si == sj && i < j)) ++c;
    }
    #pragma unroll
    for (int o = 16; o; o >>= 1) c += __shfl_down_sync(0xffffffffu, c, o);
    if ((tid & 31) == 0) sr[tid >> 5] = c;
    __syncthreads();
    if (tid == 0) {
        int r = 0;
        #pragma unroll
        for (int w = 0; w < 8; ++w) r += sr[w];
        g_sel[j] = (r < TOPN) ? 1 : 0;
    }
}

// ---------------- 5. contrast term per selected column ---------------------
__global__ void __launch_bounds__(256) contrast_kernel(const int* __restrict__ slab)
{
    const int j = blockIdx.x;
    const int tid = threadIdx.x;
    __shared__ float s_m[8];
    __shared__ float s_pA[8];
    __shared__ float s_pM[8];

    if (!g_sel[j]) { if (tid == 0) g_logt[j] = 0.0f; return; }

    const float* row = g_sim0T + (size_t)j * NSRC;
    const int a = g_assigned[j];

    float m = -INFINITY;
    for (int i = tid; i < NSRC; i += 256) m = fmaxf(m, row[i]);
    #pragma unroll
    for (int o = 16; o; o >>= 1) m = fmaxf(m, __shfl_down_sync(0xffffffffu, m, o));
    if ((tid & 31) == 0) s_m[tid >> 5] = m;
    __syncthreads();
    float mm = s_m[0];
    #pragma unroll
    for (int w = 1; w < 8; ++w) mm = fmaxf(mm, s_m[w]);

    float eA = 0.0f, eM = 0.0f;
    const float itau = 1.0f / TAU;
    for (int i = tid; i < NSRC; i += 256) {
        const float e = expf((row[i] - mm) * itau);
        eA += e;
        if (slab[i] == a) eM += e;
    }
    #pragma unroll
    for (int o = 16; o; o >>= 1) {
        eA += __shfl_down_sync(0xffffffffu, eA, o);
        eM += __shfl_down_sync(0xffffffffu, eM, o);
    }
    if ((tid & 31) == 0) { s_pA[tid >> 5] = eA; s_pM[tid >> 5] = eM; }
    __syncthreads();
    if (tid == 0) {
        float tA = 0.0f, tM = 0.0f;
        #pragma unroll
        for (int w = 0; w < 8; ++w) { tA += s_pA[w]; tM += s_pM[w]; }
        g_logt[j] = logf(tM / tA + EPSL);
    }
}

// ---------------- 6. final deterministic reduction --------------------------
__global__ void __launch_bounds__(256) finalize_kernel(float* out, int out_size)
{
    const int tid = threadIdx.x;
    __shared__ float sr[8];
    float acc = 0.0f;
    for (int i = tid; i < NTGT; i += 256) acc += g_logt[i];
    #pragma unroll
    for (int o = 16; o; o >>= 1) acc += __shfl_down_sync(0xffffffffu, acc, o);
    if ((tid & 31) == 0) sr[tid >> 5] = acc;
    __syncthreads();
    if (tid == 0) {
        float tot = 0.0f;
        #pragma unroll
        for (int w = 0; w < 8; ++w) tot += sr[w];
        out[0] = -(tot / (float)TOPN);
        if (out_size > 1) out[1] = (float)g_nc;
    }
}

// ---------------- host launcher ---------------------------------------------
extern "C" void kernel_launch(void* const* d_in, const int* in_sizes, int n_in,
                              void* d_out, int out_size)
{
    const float* src  = (const float*)d_in[0];
    const int*   slab = (const int*)  d_in[1];
    const float* tgt  = (const float*)d_in[2];
    const float* tgt0 = (const float*)d_in[3];
    const int*   tlab = (const int*)  d_in[4];
    float* out = (float*)d_out;

    cudaFuncSetAttribute(gemm_f16, cudaFuncAttributeMaxDynamicSharedMemorySize,
                         GEMM_SMEM);

    normalize_k<<<dim3(NSRC, 3), 128>>>(src, tgt, tgt0);
    gemm_f16<<<dim3(32, 32), 256, GEMM_SMEM>>>(0, KSPL);  // simT
    gemm_f16<<<dim3(32, 32), 256, GEMM_SMEM>>>(1, KSPL);  // sim0T
    rank_kernel<<<NTGT, 256>>>(slab, tlab);
    select_kernel<<<NTGT, 256>>>();
    contrast_kernel<<<NTGT, 256>>>(slab);
    finalize_kernel<<<1, 256>>>(out, out_size);
}